// round 5
// baseline (speedup 1.0000x reference)
#include <cuda_runtime.h>
#include <cuda_bf16.h>
#include <math.h>

// Problem constants
#define BB 2
#define TT 2048
#define HID 4096
#define HH 32
#define KVH 4
#define DD 128
#define GROUP 8
#define QKV_OUT ((HH + 2*KVH)*DD)   // 5120
#define MT (BB*TT)                  // 4096
#define SCALE_F 0.08838834764831845f

// ---------------- scratch (device globals; no allocations allowed) ------------
__device__ float g_qkv[(size_t)MT * QKV_OUT];     // 4096 x 5120
__device__ float g_q[(size_t)BB * HH * TT * DD];  // [b,h,t,d]
__device__ float g_k[(size_t)BB * KVH * TT * DD]; // [b,kv,t,d]
__device__ float g_v[(size_t)BB * KVH * TT * DD];
__device__ float g_ao[(size_t)MT * HH * DD];      // [b,t,h,d] == [m, o]

// ---------------- SGEMM: C[M,N] = A[M,K] * B[N,K]^T (both row-major, K contig) -
#define GBM 128
#define GBN 128
#define GBK 16
#define GAS 132   // padded smem row stride

__global__ __launch_bounds__(256) void gemm_nt(const float* __restrict__ A,
                                               const float* __restrict__ Bw,
                                               float* __restrict__ C,
                                               int M, int N, int K) {
    __shared__ float As[GBK][GAS];
    __shared__ float Bs[GBK][GAS];
    const int tid = threadIdx.x;
    const int tx = tid & 15, ty = tid >> 4;
    const int bm = blockIdx.y * GBM, bn = blockIdx.x * GBN;

    const float* aptr = A + (size_t)bm * K;
    const float* bptr = Bw + (size_t)bn * K;

    float acc[8][8];
#pragma unroll
    for (int i = 0; i < 8; i++)
#pragma unroll
        for (int j = 0; j < 8; j++) acc[i][j] = 0.f;

    for (int k0 = 0; k0 < K; k0 += GBK) {
        // load 128x16 tiles of A and B (transposed into smem: [k][m])
#pragma unroll
        for (int li = 0; li < 2; li++) {
            int i = tid + li * 256;          // 0..511
            int r = i >> 2;
            int kc = (i & 3) << 2;
            float4 a4 = *(const float4*)(aptr + (size_t)r * K + k0 + kc);
            As[kc + 0][r] = a4.x; As[kc + 1][r] = a4.y;
            As[kc + 2][r] = a4.z; As[kc + 3][r] = a4.w;
            float4 b4 = *(const float4*)(bptr + (size_t)r * K + k0 + kc);
            Bs[kc + 0][r] = b4.x; Bs[kc + 1][r] = b4.y;
            Bs[kc + 2][r] = b4.z; Bs[kc + 3][r] = b4.w;
        }
        __syncthreads();
#pragma unroll
        for (int kk = 0; kk < GBK; kk++) {
            float af[8], bf[8];
            *(float4*)(af)     = *(const float4*)&As[kk][ty * 8];
            *(float4*)(af + 4) = *(const float4*)&As[kk][ty * 8 + 4];
            *(float4*)(bf)     = *(const float4*)&Bs[kk][tx * 8];
            *(float4*)(bf + 4) = *(const float4*)&Bs[kk][tx * 8 + 4];
#pragma unroll
            for (int i = 0; i < 8; i++)
#pragma unroll
                for (int j = 0; j < 8; j++)
                    acc[i][j] = fmaf(af[i], bf[j], acc[i][j]);
        }
        __syncthreads();
    }
#pragma unroll
    for (int i = 0; i < 8; i++) {
        float* crow = C + (size_t)(bm + ty * 8 + i) * N + bn + tx * 8;
        float4 c0 = make_float4(acc[i][0], acc[i][1], acc[i][2], acc[i][3]);
        float4 c1 = make_float4(acc[i][4], acc[i][5], acc[i][6], acc[i][7]);
        *(float4*)(crow)     = c0;
        *(float4*)(crow + 4) = c1;
    }
}

// ---------------- "RMSNorm" (reference semantics!) + RoPE + scatter ----------
// NOTE: the reference does   q = rsqrt(mean(q*q) + eps) * q_weight
// i.e. the original q values are NOT multiplied back in. Only the norm scalar
// (per b,h,t) times the weight vector survives. We replicate that exactly.
__global__ void norm_rope_kernel(const float* __restrict__ qkv,
                                 const float* __restrict__ qw,
                                 const float* __restrict__ kw,
                                 float* __restrict__ Qo,
                                 float* __restrict__ Ko,
                                 float* __restrict__ Vo) {
    const int m = blockIdx.x;       // token index 0..MT-1
    const int hy = blockIdx.y;      // 0..H+2*KV-1
    const int b = m / TT, t = m % TT;
    const int d = threadIdx.x;      // 0..127

    const float* src = qkv + (size_t)m * QKV_OUT + (size_t)hy * DD;
    float x = src[d];

    __shared__ float sh[DD];
    __shared__ float red[4];

    if (hy < HH + KVH) {
        // sum of squares over D
        float ss = x * x;
#pragma unroll
        for (int o = 16; o; o >>= 1) ss += __shfl_xor_sync(0xffffffffu, ss, o);
        if ((d & 31) == 0) red[d >> 5] = ss;
        __syncthreads();
        float tot = red[0] + red[1] + red[2] + red[3];
        float r = rsqrtf(tot * (1.0f / DD) + 1e-6f);
        float w = (hy < HH) ? qw[hy * DD + d] : kw[(hy - HH) * DD + d];
        sh[d] = r * w;                 // <-- reference semantics: x dropped
        __syncthreads();
        // RoPE
        int i = d & 63;
        double invf = exp(-(double)i / 64.0 * log(10000.0));
        double th = (double)t * invf;
        float c = (float)cos(th);
        float s = (float)sin(th);
        float x1 = sh[i], x2 = sh[i + 64];
        float out = (d < 64) ? (x1 * c - x2 * s) : (x1 * s + x2 * c);
        if (hy < HH)
            Qo[(((size_t)b * HH + hy) * TT + t) * DD + d] = out;
        else
            Ko[(((size_t)b * KVH + (hy - HH)) * TT + t) * DD + d] = out;
    } else {
        int vh = hy - HH - KVH;
        Vo[(((size_t)b * KVH + vh) * TT + t) * DD + d] = x;
    }
}

// ---------------- Flash attention (fp32, online softmax) ---------------------
#define BQ 64
#define BK 64
#define QSS 129   // padded stride for Q/K/V tiles
#define SSS 65    // padded stride for S tile
#define ATTN_SMEM ((2 * BQ * QSS + BQ * SSS + 3 * BQ) * 4)

__global__ __launch_bounds__(256) void attn_kernel(const float* __restrict__ Qg,
                                                   const float* __restrict__ Kg,
                                                   const float* __restrict__ Vg,
                                                   float* __restrict__ Og) {
    extern __shared__ float sm[];
    float* Qs   = sm;                       // [BQ][QSS]
    float* KVs  = Qs + BQ * QSS;            // [BK][QSS]
    float* Ss   = KVs + BK * QSS;           // [BQ][SSS]
    float* mrow = Ss + BQ * SSS;            // [BQ]
    float* lrow = mrow + BQ;
    float* arow = lrow + BQ;

    const int tid = threadIdx.x;
    const int qt = blockIdx.x, h = blockIdx.y, b = blockIdx.z;
    const int kvh = h / GROUP;

    const float* qptr  = Qg + (((size_t)b * HH + h) * TT + (size_t)qt * BQ) * DD;
    const float* kbase = Kg + ((size_t)b * KVH + kvh) * TT * DD;
    const float* vbase = Vg + ((size_t)b * KVH + kvh) * TT * DD;

    // load Q tile (64 x 128)
    for (int i = tid; i < BQ * DD / 4; i += 256) {
        int r = i >> 5, c = (i & 31) << 2;
        float4 t4 = *(const float4*)(qptr + (size_t)r * DD + c);
        float* dst = Qs + r * QSS + c;
        dst[0] = t4.x; dst[1] = t4.y; dst[2] = t4.z; dst[3] = t4.w;
    }
    if (tid < BQ) { mrow[tid] = -1e30f; lrow[tid] = 0.f; }

    const int sr = (tid >> 4) * 4;   // S microtile rows
    const int sc = (tid & 15) * 4;   // S microtile cols
    const int pr = (tid & 15) * 4;   // O rows for PV step
    const int pc = (tid >> 4) * 8;   // O cols (d) for PV step

    float oacc[4][8];
#pragma unroll
    for (int i = 0; i < 4; i++)
#pragma unroll
        for (int j = 0; j < 8; j++) oacc[i][j] = 0.f;

    __syncthreads();

    for (int kt = 0; kt < TT / BK; kt++) {
        // load K tile
        for (int i = tid; i < BK * DD / 4; i += 256) {
            int r = i >> 5, c = (i & 31) << 2;
            float4 t4 = *(const float4*)(kbase + ((size_t)kt * BK + r) * DD + c);
            float* dst = KVs + r * QSS + c;
            dst[0] = t4.x; dst[1] = t4.y; dst[2] = t4.z; dst[3] = t4.w;
        }
        __syncthreads();

        // S = Q K^T * SCALE  (4x4 per thread)
        float sa[4][4];
#pragma unroll
        for (int i = 0; i < 4; i++)
#pragma unroll
            for (int j = 0; j < 4; j++) sa[i][j] = 0.f;
#pragma unroll 4
        for (int kk = 0; kk < DD; kk++) {
            float qf[4], kf[4];
#pragma unroll
            for (int i = 0; i < 4; i++) qf[i] = Qs[(sr + i) * QSS + kk];
#pragma unroll
            for (int j = 0; j < 4; j++) kf[j] = KVs[(sc + j) * QSS + kk];
#pragma unroll
            for (int i = 0; i < 4; i++)
#pragma unroll
                for (int j = 0; j < 4; j++)
                    sa[i][j] = fmaf(qf[i], kf[j], sa[i][j]);
        }
#pragma unroll
        for (int i = 0; i < 4; i++)
#pragma unroll
            for (int j = 0; j < 4; j++)
                Ss[(sr + i) * SSS + sc + j] = sa[i][j] * SCALE_F;
        __syncthreads();

        // softmax by threads 0..63 (one row each); V load by threads 64..255
        if (tid < BQ) {
            float m_old = mrow[tid];
            float mx = m_old;
            float* srow = Ss + tid * SSS;
            for (int j = 0; j < BK; j++) mx = fmaxf(mx, srow[j]);
            float alpha = expf(m_old - mx);
            float lsum = 0.f;
            for (int j = 0; j < BK; j++) {
                float p = expf(srow[j] - mx);
                srow[j] = p;
                lsum += p;
            }
            mrow[tid] = mx;
            lrow[tid] = lrow[tid] * alpha + lsum;
            arow[tid] = alpha;
        } else {
            for (int i = tid - 64; i < BK * DD / 4; i += 192) {
                int r = i >> 5, c = (i & 31) << 2;
                float4 t4 = *(const float4*)(vbase + ((size_t)kt * BK + r) * DD + c);
                float* dst = KVs + r * QSS + c;
                dst[0] = t4.x; dst[1] = t4.y; dst[2] = t4.z; dst[3] = t4.w;
            }
        }
        __syncthreads();

        // rescale O and accumulate P * V  (4 rows x 8 cols per thread)
        float alphas[4];
#pragma unroll
        for (int i = 0; i < 4; i++) alphas[i] = arow[pr + i];
#pragma unroll
        for (int i = 0; i < 4; i++)
#pragma unroll
            for (int dd = 0; dd < 8; dd++) oacc[i][dd] *= alphas[i];

#pragma unroll 2
        for (int j = 0; j < BK; j++) {
            float pv[4], vv[8];
#pragma unroll
            for (int i = 0; i < 4; i++) pv[i] = Ss[(pr + i) * SSS + j];
#pragma unroll
            for (int dd = 0; dd < 8; dd++) vv[dd] = KVs[j * QSS + pc + dd];
#pragma unroll
            for (int i = 0; i < 4; i++)
#pragma unroll
                for (int dd = 0; dd < 8; dd++)
                    oacc[i][dd] = fmaf(pv[i], vv[dd], oacc[i][dd]);
        }
        __syncthreads();  // before next K load overwrites KVs
    }

    // write O: [b, t, h, d]
#pragma unroll
    for (int i = 0; i < 4; i++) {
        float inv = 1.0f / lrow[pr + i];
        int t = qt * BQ + pr + i;
        float* dst = Og + (((size_t)b * TT + t) * HH + h) * DD + pc;
#pragma unroll
        for (int dd = 0; dd < 8; dd++) dst[dd] = oacc[i][dd] * inv;
    }
}

// ---------------- launch ------------------------------------------------------
extern "C" void kernel_launch(void* const* d_in, const int* in_sizes, int n_in,
                              void* d_out, int out_size) {
    const float* hidden = (const float*)d_in[0];  // [B,T,HID]
    const float* Wqkv   = (const float*)d_in[1];  // [QKV_OUT, HID]
    const float* Wo     = (const float*)d_in[2];  // [HID, H*D]
    const float* qw     = (const float*)d_in[3];  // [H, D]
    const float* kw     = (const float*)d_in[4];  // [KV, D]
    float* out = (float*)d_out;                   // [B,T,HID]

    float *qkv, *qb, *kb, *vb, *ao;
    cudaGetSymbolAddress((void**)&qkv, g_qkv);
    cudaGetSymbolAddress((void**)&qb,  g_q);
    cudaGetSymbolAddress((void**)&kb,  g_k);
    cudaGetSymbolAddress((void**)&vb,  g_v);
    cudaGetSymbolAddress((void**)&ao,  g_ao);

    cudaFuncSetAttribute(attn_kernel, cudaFuncAttributeMaxDynamicSharedMemorySize,
                         ATTN_SMEM);

    // 1) QKV projection: [MT, HID] x [QKV_OUT, HID]^T -> [MT, QKV_OUT]
    {
        dim3 grid(QKV_OUT / GBN, MT / GBM);
        gemm_nt<<<grid, 256>>>(hidden, Wqkv, qkv, MT, QKV_OUT, HID);
    }

    // 2) norm scalar + RoPE + layout
    {
        dim3 grid(MT, HH + 2 * KVH);
        norm_rope_kernel<<<grid, DD>>>(qkv, qw, kw, qb, kb, vb);
    }

    // 3) Attention
    {
        dim3 grid(TT / BQ, HH, BB);
        attn_kernel<<<grid, 256, ATTN_SMEM>>>(qb, kb, vb, ao);
    }

    // 4) Output projection: [MT, H*D] x [HID, H*D]^T -> [MT, HID]
    {
        dim3 grid(HID / GBN, MT / GBM);
        gemm_nt<<<grid, 256>>>(ao, Wo, out, MT, HH * DD, HID);
    }
}

// round 10
// speedup vs baseline: 1.3313x; 1.3313x over previous
#include <cuda_runtime.h>
#include <cuda_bf16.h>
#include <math.h>
#include <stdint.h>

// Problem constants
#define BB 2
#define TT 2048
#define HID 4096
#define HH 32
#define KVH 4
#define DD 128
#define GROUP 8
#define QKV_OUT ((HH + 2*KVH)*DD)   // 5120
#define MT (BB*TT)                  // 4096
#define KDIM 4096                   // K for both big GEMMs
#define SCALE_F 0.08838834764831845f

// ---------------- scratch (device globals; no allocations allowed) ------------
__device__ float g_qkv[(size_t)MT * QKV_OUT];     // 4096 x 5120
__device__ float g_q[(size_t)BB * HH * TT * DD];  // [b,h,t,d]
__device__ float g_k[(size_t)BB * KVH * TT * DD]; // [b,kv,t,d]
__device__ float g_v[(size_t)BB * KVH * TT * DD];
__device__ float g_ao[(size_t)MT * HH * DD];      // [b,t,h,d] == [m, o]

// bf16 hi/lo split buffers for tensor-core GEMMs
__device__ __nv_bfloat16 g_ahi[(size_t)MT * KDIM];
__device__ __nv_bfloat16 g_alo[(size_t)MT * KDIM];
__device__ __nv_bfloat16 g_bhi[(size_t)QKV_OUT * KDIM];
__device__ __nv_bfloat16 g_blo[(size_t)QKV_OUT * KDIM];

// ================= hi/lo conversion ==========================================
__global__ void cvt_hilo(const float* __restrict__ src,
                         __nv_bfloat16* __restrict__ hi,
                         __nv_bfloat16* __restrict__ lo, size_t n) {
    size_t i = (size_t)blockIdx.x * blockDim.x + threadIdx.x;
    size_t stride = (size_t)gridDim.x * blockDim.x;
    for (; i < n / 4; i += stride) {
        float4 x = ((const float4*)src)[i];
        __nv_bfloat16 h0 = __float2bfloat16(x.x);
        __nv_bfloat16 h1 = __float2bfloat16(x.y);
        __nv_bfloat16 h2 = __float2bfloat16(x.z);
        __nv_bfloat16 h3 = __float2bfloat16(x.w);
        __nv_bfloat16 l0 = __float2bfloat16(x.x - __bfloat162float(h0));
        __nv_bfloat16 l1 = __float2bfloat16(x.y - __bfloat162float(h1));
        __nv_bfloat16 l2 = __float2bfloat16(x.z - __bfloat162float(h2));
        __nv_bfloat16 l3 = __float2bfloat16(x.w - __bfloat162float(h3));
        __nv_bfloat162 hp0, hp1, lp0, lp1;
        hp0.x = h0; hp0.y = h1; hp1.x = h2; hp1.y = h3;
        lp0.x = l0; lp0.y = l1; lp1.x = l2; lp1.y = l3;
        ((__nv_bfloat162*)hi)[i * 2 + 0] = hp0;
        ((__nv_bfloat162*)hi)[i * 2 + 1] = hp1;
        ((__nv_bfloat162*)lo)[i * 2 + 0] = lp0;
        ((__nv_bfloat162*)lo)[i * 2 + 1] = lp1;
    }
}

// ================= HMMA GEMM: C[M,N] = A[M,K] * B[N,K]^T =====================
// bf16 hi/lo 3-pass via mma.sync.m16n8k16 (compute_103-compatible, no tcgen05).
// Block 128x128, 8 warps (2m x 4n), warp tile 64x32 (4x4 m16n8k16 tiles), BK=32.
#define GBK2 32
#define SSTR 40   // bf16 elems per smem row (32 data + 8 pad); 80B, 16B-aligned

__device__ __forceinline__ void mma16816(float* c, const uint32_t* a, const uint32_t* b) {
    asm volatile("mma.sync.aligned.m16n8k16.row.col.f32.bf16.bf16.f32 "
                 "{%0,%1,%2,%3}, {%4,%5,%6,%7}, {%8,%9}, {%0,%1,%2,%3};"
                 : "+f"(c[0]), "+f"(c[1]), "+f"(c[2]), "+f"(c[3])
                 : "r"(a[0]), "r"(a[1]), "r"(a[2]), "r"(a[3]),
                   "r"(b[0]), "r"(b[1]));
}

__global__ __launch_bounds__(256) void hmma_gemm(const __nv_bfloat16* __restrict__ Ah,
                                                 const __nv_bfloat16* __restrict__ Al,
                                                 const __nv_bfloat16* __restrict__ Bh,
                                                 const __nv_bfloat16* __restrict__ Bl,
                                                 float* __restrict__ C, int N) {
    __shared__ __nv_bfloat16 sAh[128 * SSTR];
    __shared__ __nv_bfloat16 sAl[128 * SSTR];
    __shared__ __nv_bfloat16 sBh[128 * SSTR];
    __shared__ __nv_bfloat16 sBl[128 * SSTR];

    const int tid  = threadIdx.x;
    const int lane = tid & 31;
    const int warp = tid >> 5;
    const int wm = (warp & 1) * 64;      // warp m offset within block
    const int wn = (warp >> 1) * 32;     // warp n offset within block
    const int g  = lane >> 2;            // 0..7
    const int tg = lane & 3;             // 0..3

    const int bm = blockIdx.y * 128;
    const int bn = blockIdx.x * 128;

    const __nv_bfloat16* gsrc[4];
    gsrc[0] = Ah + (size_t)bm * KDIM;
    gsrc[1] = Al + (size_t)bm * KDIM;
    gsrc[2] = Bh + (size_t)bn * KDIM;
    gsrc[3] = Bl + (size_t)bn * KDIM;
    __nv_bfloat16* ssrc[4] = { sAh, sAl, sBh, sBl };

    float acc[4][4][4];
#pragma unroll
    for (int mt = 0; mt < 4; mt++)
#pragma unroll
        for (int nt = 0; nt < 4; nt++)
#pragma unroll
            for (int e = 0; e < 4; e++) acc[mt][nt][e] = 0.f;

    for (int k0 = 0; k0 < KDIM; k0 += GBK2) {
        // stage 4 tiles of 128 rows x 32 bf16
#pragma unroll
        for (int t = 0; t < 4; t++) {
#pragma unroll
            for (int j = 0; j < 2; j++) {
                int slot = tid + j * 256;            // 0..511
                int row = slot >> 2;
                int c8 = (slot & 3) * 8;
                uint4 v = *(const uint4*)(gsrc[t] + (size_t)row * KDIM + k0 + c8);
                *(uint4*)(ssrc[t] + row * SSTR + c8) = v;
            }
        }
        __syncthreads();

#pragma unroll
        for (int ks = 0; ks < 2; ks++) {
            const int kk = ks * 16;
            uint32_t ah[4][4], al[4][4], bh[4][2], bl[4][2];
#pragma unroll
            for (int mt = 0; mt < 4; mt++) {
                int r = wm + mt * 16 + g;
                const __nv_bfloat16* p0 = sAh + r * SSTR + kk + tg * 2;
                const __nv_bfloat16* p1 = sAh + (r + 8) * SSTR + kk + tg * 2;
                ah[mt][0] = *(const uint32_t*)(p0);
                ah[mt][1] = *(const uint32_t*)(p1);
                ah[mt][2] = *(const uint32_t*)(p0 + 8);
                ah[mt][3] = *(const uint32_t*)(p1 + 8);
                const __nv_bfloat16* q0 = sAl + r * SSTR + kk + tg * 2;
                const __nv_bfloat16* q1 = sAl + (r + 8) * SSTR + kk + tg * 2;
                al[mt][0] = *(const uint32_t*)(q0);
                al[mt][1] = *(const uint32_t*)(q1);
                al[mt][2] = *(const uint32_t*)(q0 + 8);
                al[mt][3] = *(const uint32_t*)(q1 + 8);
            }
#pragma unroll
            for (int nt = 0; nt < 4; nt++) {
                int rb = wn + nt * 8 + g;
                const __nv_bfloat16* p = sBh + rb * SSTR + kk + tg * 2;
                bh[nt][0] = *(const uint32_t*)(p);
                bh[nt][1] = *(const uint32_t*)(p + 8);
                const __nv_bfloat16* q = sBl + rb * SSTR + kk + tg * 2;
                bl[nt][0] = *(const uint32_t*)(q);
                bl[nt][1] = *(const uint32_t*)(q + 8);
            }
#pragma unroll
            for (int mt = 0; mt < 4; mt++)
#pragma unroll
                for (int nt = 0; nt < 4; nt++) {
                    mma16816(acc[mt][nt], ah[mt], bh[nt]);
                    mma16816(acc[mt][nt], ah[mt], bl[nt]);
                    mma16816(acc[mt][nt], al[mt], bh[nt]);
                }
        }
        __syncthreads();
    }

    // epilogue: c0,c1 -> (row g, cols 2tg,2tg+1); c2,c3 -> row g+8
#pragma unroll
    for (int mt = 0; mt < 4; mt++) {
#pragma unroll
        for (int nt = 0; nt < 4; nt++) {
            int row = bm + wm + mt * 16 + g;
            int col = bn + wn + nt * 8 + tg * 2;
            *(float2*)(C + (size_t)row * N + col) =
                make_float2(acc[mt][nt][0], acc[mt][nt][1]);
            *(float2*)(C + (size_t)(row + 8) * N + col) =
                make_float2(acc[mt][nt][2], acc[mt][nt][3]);
        }
    }
}

// ---------------- "RMSNorm" (reference semantics!) + RoPE + scatter ----------
// reference: q = rsqrt(mean(q*q)+eps) * q_weight   (original q NOT multiplied in)
__global__ void norm_rope_kernel(const float* __restrict__ qkv,
                                 const float* __restrict__ qw,
                                 const float* __restrict__ kw,
                                 float* __restrict__ Qo,
                                 float* __restrict__ Ko,
                                 float* __restrict__ Vo) {
    const int m = blockIdx.x;
    const int hy = blockIdx.y;
    const int b = m / TT, t = m % TT;
    const int d = threadIdx.x;

    const float* src = qkv + (size_t)m * QKV_OUT + (size_t)hy * DD;
    float x = src[d];

    __shared__ float sh[DD];
    __shared__ float red[4];

    if (hy < HH + KVH) {
        float ss = x * x;
#pragma unroll
        for (int o = 16; o; o >>= 1) ss += __shfl_xor_sync(0xffffffffu, ss, o);
        if ((d & 31) == 0) red[d >> 5] = ss;
        __syncthreads();
        float tot = red[0] + red[1] + red[2] + red[3];
        float r = rsqrtf(tot * (1.0f / DD) + 1e-6f);
        float w = (hy < HH) ? qw[hy * DD + d] : kw[(hy - HH) * DD + d];
        sh[d] = r * w;
        __syncthreads();
        int i = d & 63;
        double invf = exp(-(double)i / 64.0 * log(10000.0));
        double th = (double)t * invf;
        float c = (float)cos(th);
        float s = (float)sin(th);
        float x1 = sh[i], x2 = sh[i + 64];
        float out = (d < 64) ? (x1 * c - x2 * s) : (x1 * s + x2 * c);
        if (hy < HH)
            Qo[(((size_t)b * HH + hy) * TT + t) * DD + d] = out;
        else
            Ko[(((size_t)b * KVH + (hy - HH)) * TT + t) * DD + d] = out;
    } else {
        int vh = hy - HH - KVH;
        Vo[(((size_t)b * KVH + vh) * TT + t) * DD + d] = x;
    }
}

// ---------------- Flash attention (fp32, online softmax) ---------------------
#define BQ 64
#define BK 64
#define QSS 129
#define SSS 65
#define ATTN_SMEM ((2 * BQ * QSS + BQ * SSS + 3 * BQ) * 4)

__global__ __launch_bounds__(256) void attn_kernel(const float* __restrict__ Qg,
                                                   const float* __restrict__ Kg,
                                                   const float* __restrict__ Vg,
                                                   float* __restrict__ Og) {
    extern __shared__ float sm[];
    float* Qs   = sm;
    float* KVs  = Qs + BQ * QSS;
    float* Ss   = KVs + BK * QSS;
    float* mrow = Ss + BQ * SSS;
    float* lrow = mrow + BQ;
    float* arow = lrow + BQ;

    const int tid = threadIdx.x;
    const int qt = blockIdx.x, h = blockIdx.y, b = blockIdx.z;
    const int kvh = h / GROUP;

    const float* qptr  = Qg + (((size_t)b * HH + h) * TT + (size_t)qt * BQ) * DD;
    const float* kbase = Kg + ((size_t)b * KVH + kvh) * TT * DD;
    const float* vbase = Vg + ((size_t)b * KVH + kvh) * TT * DD;

    for (int i = tid; i < BQ * DD / 4; i += 256) {
        int r = i >> 5, c = (i & 31) << 2;
        float4 t4 = *(const float4*)(qptr + (size_t)r * DD + c);
        float* dst = Qs + r * QSS + c;
        dst[0] = t4.x; dst[1] = t4.y; dst[2] = t4.z; dst[3] = t4.w;
    }
    if (tid < BQ) { mrow[tid] = -1e30f; lrow[tid] = 0.f; }

    const int sr = (tid >> 4) * 4;
    const int sc = (tid & 15) * 4;
    const int pr = (tid & 15) * 4;
    const int pc = (tid >> 4) * 8;

    float oacc[4][8];
#pragma unroll
    for (int i = 0; i < 4; i++)
#pragma unroll
        for (int j = 0; j < 8; j++) oacc[i][j] = 0.f;

    __syncthreads();

    for (int kt = 0; kt < TT / BK; kt++) {
        for (int i = tid; i < BK * DD / 4; i += 256) {
            int r = i >> 5, c = (i & 31) << 2;
            float4 t4 = *(const float4*)(kbase + ((size_t)kt * BK + r) * DD + c);
            float* dst = KVs + r * QSS + c;
            dst[0] = t4.x; dst[1] = t4.y; dst[2] = t4.z; dst[3] = t4.w;
        }
        __syncthreads();

        float sa[4][4];
#pragma unroll
        for (int i = 0; i < 4; i++)
#pragma unroll
            for (int j = 0; j < 4; j++) sa[i][j] = 0.f;
#pragma unroll 4
        for (int kk = 0; kk < DD; kk++) {
            float qf[4], kf[4];
#pragma unroll
            for (int i = 0; i < 4; i++) qf[i] = Qs[(sr + i) * QSS + kk];
#pragma unroll
            for (int j = 0; j < 4; j++) kf[j] = KVs[(sc + j) * QSS + kk];
#pragma unroll
            for (int i = 0; i < 4; i++)
#pragma unroll
                for (int j = 0; j < 4; j++)
                    sa[i][j] = fmaf(qf[i], kf[j], sa[i][j]);
        }
#pragma unroll
        for (int i = 0; i < 4; i++)
#pragma unroll
            for (int j = 0; j < 4; j++)
                Ss[(sr + i) * SSS + sc + j] = sa[i][j] * SCALE_F;
        __syncthreads();

        if (tid < BQ) {
            float m_old = mrow[tid];
            float mx = m_old;
            float* srow = Ss + tid * SSS;
            for (int j = 0; j < BK; j++) mx = fmaxf(mx, srow[j]);
            float alpha = expf(m_old - mx);
            float lsum = 0.f;
            for (int j = 0; j < BK; j++) {
                float p = expf(srow[j] - mx);
                srow[j] = p;
                lsum += p;
            }
            mrow[tid] = mx;
            lrow[tid] = lrow[tid] * alpha + lsum;
            arow[tid] = alpha;
        } else {
            for (int i = tid - 64; i < BK * DD / 4; i += 192) {
                int r = i >> 5, c = (i & 31) << 2;
                float4 t4 = *(const float4*)(vbase + ((size_t)kt * BK + r) * DD + c);
                float* dst = KVs + r * QSS + c;
                dst[0] = t4.x; dst[1] = t4.y; dst[2] = t4.z; dst[3] = t4.w;
            }
        }
        __syncthreads();

        float alphas[4];
#pragma unroll
        for (int i = 0; i < 4; i++) alphas[i] = arow[pr + i];
#pragma unroll
        for (int i = 0; i < 4; i++)
#pragma unroll
            for (int dd = 0; dd < 8; dd++) oacc[i][dd] *= alphas[i];

#pragma unroll 2
        for (int j = 0; j < BK; j++) {
            float pv[4], vv[8];
#pragma unroll
            for (int i = 0; i < 4; i++) pv[i] = Ss[(pr + i) * SSS + j];
#pragma unroll
            for (int dd = 0; dd < 8; dd++) vv[dd] = KVs[j * QSS + pc + dd];
#pragma unroll
            for (int i = 0; i < 4; i++)
#pragma unroll
                for (int dd = 0; dd < 8; dd++)
                    oacc[i][dd] = fmaf(pv[i], vv[dd], oacc[i][dd]);
        }
        __syncthreads();
    }

#pragma unroll
    for (int i = 0; i < 4; i++) {
        float inv = 1.0f / lrow[pr + i];
        int t = qt * BQ + pr + i;
        float* dst = Og + (((size_t)b * TT + t) * HH + h) * DD + pc;
#pragma unroll
        for (int dd = 0; dd < 8; dd++) dst[dd] = oacc[i][dd] * inv;
    }
}

// ---------------- launch ------------------------------------------------------
extern "C" void kernel_launch(void* const* d_in, const int* in_sizes, int n_in,
                              void* d_out, int out_size) {
    const float* hidden = (const float*)d_in[0];  // [B,T,HID]
    const float* Wqkv   = (const float*)d_in[1];  // [QKV_OUT, HID]
    const float* Wo     = (const float*)d_in[2];  // [HID, H*D]
    const float* qw     = (const float*)d_in[3];  // [H, D]
    const float* kw     = (const float*)d_in[4];  // [KV, D]
    float* out = (float*)d_out;                   // [B,T,HID]

    float *qkv, *qb, *kb, *vb, *ao;
    __nv_bfloat16 *ahi, *alo, *bhi, *blo;
    cudaGetSymbolAddress((void**)&qkv, g_qkv);
    cudaGetSymbolAddress((void**)&qb,  g_q);
    cudaGetSymbolAddress((void**)&kb,  g_k);
    cudaGetSymbolAddress((void**)&vb,  g_v);
    cudaGetSymbolAddress((void**)&ao,  g_ao);
    cudaGetSymbolAddress((void**)&ahi, g_ahi);
    cudaGetSymbolAddress((void**)&alo, g_alo);
    cudaGetSymbolAddress((void**)&bhi, g_bhi);
    cudaGetSymbolAddress((void**)&blo, g_blo);

    cudaFuncSetAttribute(attn_kernel, cudaFuncAttributeMaxDynamicSharedMemorySize,
                         ATTN_SMEM);

    // 1) convert inputs to bf16 hi/lo
    cvt_hilo<<<1024, 256>>>(hidden, ahi, alo, (size_t)MT * KDIM);
    cvt_hilo<<<1024, 256>>>(Wqkv, bhi, blo, (size_t)QKV_OUT * KDIM);

    // 2) QKV projection (tensor pipe via mma.sync): [MT,K] x [QKV_OUT,K]^T
    {
        dim3 grid(QKV_OUT / 128, MT / 128);
        hmma_gemm<<<grid, 256>>>(ahi, alo, bhi, blo, qkv, QKV_OUT);
    }

    // 3) norm scalar + RoPE + layout
    {
        dim3 grid(MT, HH + 2 * KVH);
        norm_rope_kernel<<<grid, DD>>>(qkv, qw, kw, qb, kb, vb);
    }

    // 4) Attention
    {
        dim3 grid(TT / BQ, HH, BB);
        attn_kernel<<<grid, 256, ATTN_SMEM>>>(qb, kb, vb, ao);
    }

    // 5) Output projection (tensor pipe via mma.sync)
    cvt_hilo<<<1024, 256>>>(ao, ahi, alo, (size_t)MT * KDIM);
    cvt_hilo<<<1024, 256>>>(Wo, bhi, blo, (size_t)HID * KDIM);
    {
        dim3 grid(HID / 128, MT / 128);
        hmma_gemm<<<grid, 256>>>(ahi, alo, bhi, blo, out, HID);
    }
}

// round 11
// speedup vs baseline: 1.9290x; 1.4490x over previous
#include <cuda_runtime.h>
#include <cuda_bf16.h>
#include <math.h>
#include <stdint.h>

// Problem constants
#define BB 2
#define TT 2048
#define HID 4096
#define HH 32
#define KVH 4
#define DD 128
#define GROUP 8
#define QKV_OUT ((HH + 2*KVH)*DD)   // 5120
#define MT (BB*TT)                  // 4096
#define KDIM 4096                   // K for both big GEMMs
#define SCALE_F 0.08838834764831845f

// ---------------- scratch (device globals; no allocations allowed) ------------
__device__ float g_qkv[(size_t)MT * QKV_OUT];     // 4096 x 5120 fp32

// bf16 hi/lo split buffers for tensor-core GEMMs
__device__ __nv_bfloat16 g_ahi[(size_t)MT * KDIM];
__device__ __nv_bfloat16 g_alo[(size_t)MT * KDIM];
__device__ __nv_bfloat16 g_bhi[(size_t)QKV_OUT * KDIM];
__device__ __nv_bfloat16 g_blo[(size_t)QKV_OUT * KDIM];

// bf16 hi/lo Q/K/V for attention ([b,h,t,d] / [b,kv,t,d])
__device__ __nv_bfloat16 g_qh[(size_t)BB * HH * TT * DD];
__device__ __nv_bfloat16 g_ql[(size_t)BB * HH * TT * DD];
__device__ __nv_bfloat16 g_kh[(size_t)BB * KVH * TT * DD];
__device__ __nv_bfloat16 g_kl[(size_t)BB * KVH * TT * DD];
__device__ __nv_bfloat16 g_vh[(size_t)BB * KVH * TT * DD];
__device__ __nv_bfloat16 g_vl[(size_t)BB * KVH * TT * DD];

// ================= helpers ===================================================
__device__ __forceinline__ void mma16816(float* c, const uint32_t* a, const uint32_t* b) {
    asm volatile("mma.sync.aligned.m16n8k16.row.col.f32.bf16.bf16.f32 "
                 "{%0,%1,%2,%3}, {%4,%5,%6,%7}, {%8,%9}, {%0,%1,%2,%3};"
                 : "+f"(c[0]), "+f"(c[1]), "+f"(c[2]), "+f"(c[3])
                 : "r"(a[0]), "r"(a[1]), "r"(a[2]), "r"(a[3]),
                   "r"(b[0]), "r"(b[1]));
}
__device__ __forceinline__ void ldsm_x4(uint32_t& r0, uint32_t& r1, uint32_t& r2,
                                        uint32_t& r3, uint32_t addr) {
    asm volatile("ldmatrix.sync.aligned.m8n8.x4.shared.b16 {%0,%1,%2,%3}, [%4];"
                 : "=r"(r0), "=r"(r1), "=r"(r2), "=r"(r3) : "r"(addr));
}
__device__ __forceinline__ void ldsm_x4_t(uint32_t& r0, uint32_t& r1, uint32_t& r2,
                                          uint32_t& r3, uint32_t addr) {
    asm volatile("ldmatrix.sync.aligned.m8n8.x4.trans.shared.b16 {%0,%1,%2,%3}, [%4];"
                 : "=r"(r0), "=r"(r1), "=r"(r2), "=r"(r3) : "r"(addr));
}
__device__ __forceinline__ uint32_t smem_u32(const void* p) {
    uint32_t a;
    asm("{ .reg .u64 t; cvta.to.shared.u64 t, %1; cvt.u32.u64 %0, t; }"
        : "=r"(a) : "l"(p));
    return a;
}
__device__ __forceinline__ uint32_t pack_bf2(float x, float y) {
    __nv_bfloat162 h = __floats2bfloat162_rn(x, y);
    return *(uint32_t*)&h;
}

// ================= hi/lo conversion ==========================================
__global__ void cvt_hilo(const float* __restrict__ src,
                         __nv_bfloat16* __restrict__ hi,
                         __nv_bfloat16* __restrict__ lo, size_t n) {
    size_t i = (size_t)blockIdx.x * blockDim.x + threadIdx.x;
    size_t stride = (size_t)gridDim.x * blockDim.x;
    for (; i < n / 4; i += stride) {
        float4 x = ((const float4*)src)[i];
        __nv_bfloat16 h0 = __float2bfloat16(x.x);
        __nv_bfloat16 h1 = __float2bfloat16(x.y);
        __nv_bfloat16 h2 = __float2bfloat16(x.z);
        __nv_bfloat16 h3 = __float2bfloat16(x.w);
        __nv_bfloat16 l0 = __float2bfloat16(x.x - __bfloat162float(h0));
        __nv_bfloat16 l1 = __float2bfloat16(x.y - __bfloat162float(h1));
        __nv_bfloat16 l2 = __float2bfloat16(x.z - __bfloat162float(h2));
        __nv_bfloat16 l3 = __float2bfloat16(x.w - __bfloat162float(h3));
        __nv_bfloat162 hp0, hp1, lp0, lp1;
        hp0.x = h0; hp0.y = h1; hp1.x = h2; hp1.y = h3;
        lp0.x = l0; lp0.y = l1; lp1.x = l2; lp1.y = l3;
        ((__nv_bfloat162*)hi)[i * 2 + 0] = hp0;
        ((__nv_bfloat162*)hi)[i * 2 + 1] = hp1;
        ((__nv_bfloat162*)lo)[i * 2 + 0] = lp0;
        ((__nv_bfloat162*)lo)[i * 2 + 1] = lp1;
    }
}

// ================= HMMA GEMM: C[M,N] = A[M,K] * B[N,K]^T =====================
#define GBK2 32
#define SSTR 40

__global__ __launch_bounds__(256) void hmma_gemm(const __nv_bfloat16* __restrict__ Ah,
                                                 const __nv_bfloat16* __restrict__ Al,
                                                 const __nv_bfloat16* __restrict__ Bh,
                                                 const __nv_bfloat16* __restrict__ Bl,
                                                 float* __restrict__ C, int N) {
    __shared__ __nv_bfloat16 sAh[128 * SSTR];
    __shared__ __nv_bfloat16 sAl[128 * SSTR];
    __shared__ __nv_bfloat16 sBh[128 * SSTR];
    __shared__ __nv_bfloat16 sBl[128 * SSTR];

    const int tid  = threadIdx.x;
    const int lane = tid & 31;
    const int warp = tid >> 5;
    const int wm = (warp & 1) * 64;
    const int wn = (warp >> 1) * 32;
    const int g  = lane >> 2;
    const int tg = lane & 3;

    const int bm = blockIdx.y * 128;
    const int bn = blockIdx.x * 128;

    const __nv_bfloat16* gsrc[4];
    gsrc[0] = Ah + (size_t)bm * KDIM;
    gsrc[1] = Al + (size_t)bm * KDIM;
    gsrc[2] = Bh + (size_t)bn * KDIM;
    gsrc[3] = Bl + (size_t)bn * KDIM;
    __nv_bfloat16* ssrc[4] = { sAh, sAl, sBh, sBl };

    float acc[4][4][4];
#pragma unroll
    for (int mt = 0; mt < 4; mt++)
#pragma unroll
        for (int nt = 0; nt < 4; nt++)
#pragma unroll
            for (int e = 0; e < 4; e++) acc[mt][nt][e] = 0.f;

    for (int k0 = 0; k0 < KDIM; k0 += GBK2) {
#pragma unroll
        for (int t = 0; t < 4; t++) {
#pragma unroll
            for (int j = 0; j < 2; j++) {
                int slot = tid + j * 256;
                int row = slot >> 2;
                int c8 = (slot & 3) * 8;
                uint4 v = *(const uint4*)(gsrc[t] + (size_t)row * KDIM + k0 + c8);
                *(uint4*)(ssrc[t] + row * SSTR + c8) = v;
            }
        }
        __syncthreads();

#pragma unroll
        for (int ks = 0; ks < 2; ks++) {
            const int kk = ks * 16;
            uint32_t ah[4][4], al[4][4], bh[4][2], bl[4][2];
#pragma unroll
            for (int mt = 0; mt < 4; mt++) {
                int r = wm + mt * 16 + g;
                const __nv_bfloat16* p0 = sAh + r * SSTR + kk + tg * 2;
                const __nv_bfloat16* p1 = sAh + (r + 8) * SSTR + kk + tg * 2;
                ah[mt][0] = *(const uint32_t*)(p0);
                ah[mt][1] = *(const uint32_t*)(p1);
                ah[mt][2] = *(const uint32_t*)(p0 + 8);
                ah[mt][3] = *(const uint32_t*)(p1 + 8);
                const __nv_bfloat16* q0 = sAl + r * SSTR + kk + tg * 2;
                const __nv_bfloat16* q1 = sAl + (r + 8) * SSTR + kk + tg * 2;
                al[mt][0] = *(const uint32_t*)(q0);
                al[mt][1] = *(const uint32_t*)(q1);
                al[mt][2] = *(const uint32_t*)(q0 + 8);
                al[mt][3] = *(const uint32_t*)(q1 + 8);
            }
#pragma unroll
            for (int nt = 0; nt < 4; nt++) {
                int rb = wn + nt * 8 + g;
                const __nv_bfloat16* p = sBh + rb * SSTR + kk + tg * 2;
                bh[nt][0] = *(const uint32_t*)(p);
                bh[nt][1] = *(const uint32_t*)(p + 8);
                const __nv_bfloat16* q = sBl + rb * SSTR + kk + tg * 2;
                bl[nt][0] = *(const uint32_t*)(q);
                bl[nt][1] = *(const uint32_t*)(q + 8);
            }
#pragma unroll
            for (int mt = 0; mt < 4; mt++)
#pragma unroll
                for (int nt = 0; nt < 4; nt++) {
                    mma16816(acc[mt][nt], ah[mt], bh[nt]);
                    mma16816(acc[mt][nt], ah[mt], bl[nt]);
                    mma16816(acc[mt][nt], al[mt], bh[nt]);
                }
        }
        __syncthreads();
    }

#pragma unroll
    for (int mt = 0; mt < 4; mt++) {
#pragma unroll
        for (int nt = 0; nt < 4; nt++) {
            int row = bm + wm + mt * 16 + g;
            int col = bn + wn + nt * 8 + tg * 2;
            *(float2*)(C + (size_t)row * N + col) =
                make_float2(acc[mt][nt][0], acc[mt][nt][1]);
            *(float2*)(C + (size_t)(row + 8) * N + col) =
                make_float2(acc[mt][nt][2], acc[mt][nt][3]);
        }
    }
}

// ---------------- "RMSNorm" (reference semantics) + RoPE -> bf16 hi/lo -------
// reference: q = rsqrt(mean(q*q)+eps) * q_weight   (original q NOT multiplied in)
// Q additionally pre-scaled by SCALE_F (folded out of the attention kernel).
__global__ void norm_rope_kernel(const float* __restrict__ qkv,
                                 const float* __restrict__ qw,
                                 const float* __restrict__ kw,
                                 __nv_bfloat16* __restrict__ Qh,
                                 __nv_bfloat16* __restrict__ Ql,
                                 __nv_bfloat16* __restrict__ Kh,
                                 __nv_bfloat16* __restrict__ Kl,
                                 __nv_bfloat16* __restrict__ Vh,
                                 __nv_bfloat16* __restrict__ Vl) {
    const int m = blockIdx.x;
    const int hy = blockIdx.y;
    const int b = m / TT, t = m % TT;
    const int d = threadIdx.x;

    const float* src = qkv + (size_t)m * QKV_OUT + (size_t)hy * DD;
    float x = src[d];

    __shared__ float sh[DD];
    __shared__ float red[4];

    if (hy < HH + KVH) {
        float ss = x * x;
#pragma unroll
        for (int o = 16; o; o >>= 1) ss += __shfl_xor_sync(0xffffffffu, ss, o);
        if ((d & 31) == 0) red[d >> 5] = ss;
        __syncthreads();
        float tot = red[0] + red[1] + red[2] + red[3];
        float r = rsqrtf(tot * (1.0f / DD) + 1e-6f);
        float w = (hy < HH) ? qw[hy * DD + d] : kw[(hy - HH) * DD + d];
        sh[d] = r * w;
        __syncthreads();
        int i = d & 63;
        double invf = exp(-(double)i / 64.0 * log(10000.0));
        double th = (double)t * invf;
        float c = (float)cos(th);
        float s = (float)sin(th);
        float x1 = sh[i], x2 = sh[i + 64];
        float out = (d < 64) ? (x1 * c - x2 * s) : (x1 * s + x2 * c);
        if (hy < HH) {
            out *= SCALE_F;
            __nv_bfloat16 hv = __float2bfloat16(out);
            size_t idx = (((size_t)b * HH + hy) * TT + t) * DD + d;
            Qh[idx] = hv;
            Ql[idx] = __float2bfloat16(out - __bfloat162float(hv));
        } else {
            __nv_bfloat16 hv = __float2bfloat16(out);
            size_t idx = (((size_t)b * KVH + (hy - HH)) * TT + t) * DD + d;
            Kh[idx] = hv;
            Kl[idx] = __float2bfloat16(out - __bfloat162float(hv));
        }
    } else {
        int vh = hy - HH - KVH;
        __nv_bfloat16 hv = __float2bfloat16(x);
        size_t idx = (((size_t)b * KVH + vh) * TT + t) * DD + d;
        Vh[idx] = hv;
        Vl[idx] = __float2bfloat16(x - __bfloat162float(hv));
    }
}

// ---------------- Flash attention (HMMA, hi/lo bf16, online softmax) ---------
// CTA: 128 q-rows, 8 warps (16 rows each), 64-key chunks.
// Output written directly as bf16 hi/lo into the Wo-GEMM A buffers.
#define BQA 128
#define BKA 64
#define KSTR 136   // smem row stride (bf16 elems) for K/V tiles
#define ATT_SMEM (4 * BKA * KSTR * 2)

__global__ __launch_bounds__(256) void attn_hmma(
    const __nv_bfloat16* __restrict__ Qh_, const __nv_bfloat16* __restrict__ Ql_,
    const __nv_bfloat16* __restrict__ Kh_, const __nv_bfloat16* __restrict__ Kl_,
    const __nv_bfloat16* __restrict__ Vh_, const __nv_bfloat16* __restrict__ Vl_,
    __nv_bfloat16* __restrict__ Ohi, __nv_bfloat16* __restrict__ Olo) {
    extern __shared__ __nv_bfloat16 smn[];
    __nv_bfloat16* sKh = smn;
    __nv_bfloat16* sKl = sKh + BKA * KSTR;
    __nv_bfloat16* sVh = sKl + BKA * KSTR;
    __nv_bfloat16* sVl = sVh + BKA * KSTR;
    const uint32_t uKh = smem_u32(sKh), uKl = smem_u32(sKl);
    const uint32_t uVh = smem_u32(sVh), uVl = smem_u32(sVl);

    const int tid  = threadIdx.x;
    const int lane = tid & 31;
    const int warp = tid >> 5;
    const int g  = lane >> 2;
    const int tg = lane & 3;

    const int qt = blockIdx.x, h = blockIdx.y, b = blockIdx.z;
    const int kvh = h / GROUP;
    const int row0 = warp * 16;            // warp's q-row base within CTA tile

    const __nv_bfloat16* qh_base = Qh_ + (((size_t)b * HH + h) * TT + (size_t)qt * BQA) * DD;
    const __nv_bfloat16* ql_base = Ql_ + (((size_t)b * HH + h) * TT + (size_t)qt * BQA) * DD;
    const __nv_bfloat16* kh_base = Kh_ + ((size_t)b * KVH + kvh) * TT * DD;
    const __nv_bfloat16* kl_base = Kl_ + ((size_t)b * KVH + kvh) * TT * DD;
    const __nv_bfloat16* vh_base = Vh_ + ((size_t)b * KVH + kvh) * TT * DD;
    const __nv_bfloat16* vl_base = Vl_ + ((size_t)b * KVH + kvh) * TT * DD;

    // preload Q A-fragments (8 k-steps over d=128), hi and lo
    uint32_t qfh[8][4], qfl[8][4];
#pragma unroll
    for (int ks = 0; ks < 8; ks++) {
        int d0 = ks * 16;
        const __nv_bfloat16* r0p = qh_base + (size_t)(row0 + g) * DD + d0 + 2 * tg;
        const __nv_bfloat16* r1p = qh_base + (size_t)(row0 + g + 8) * DD + d0 + 2 * tg;
        qfh[ks][0] = *(const uint32_t*)(r0p);
        qfh[ks][1] = *(const uint32_t*)(r1p);
        qfh[ks][2] = *(const uint32_t*)(r0p + 8);
        qfh[ks][3] = *(const uint32_t*)(r1p + 8);
        const __nv_bfloat16* s0p = ql_base + (size_t)(row0 + g) * DD + d0 + 2 * tg;
        const __nv_bfloat16* s1p = ql_base + (size_t)(row0 + g + 8) * DD + d0 + 2 * tg;
        qfl[ks][0] = *(const uint32_t*)(s0p);
        qfl[ks][1] = *(const uint32_t*)(s1p);
        qfl[ks][2] = *(const uint32_t*)(s0p + 8);
        qfl[ks][3] = *(const uint32_t*)(s1p + 8);
    }

    float oacc[16][4];
#pragma unroll
    for (int nt = 0; nt < 16; nt++)
#pragma unroll
        for (int e = 0; e < 4; e++) oacc[nt][e] = 0.f;
    float m0 = -1e30f, m1 = -1e30f, l0 = 0.f, l1 = 0.f;

    for (int kt = 0; kt < TT / BKA; kt++) {
        // stage K and V (hi/lo) tiles: 64 rows x 128 d
        const __nv_bfloat16* kh_src = kh_base + (size_t)kt * BKA * DD;
        const __nv_bfloat16* kl_src = kl_base + (size_t)kt * BKA * DD;
        const __nv_bfloat16* vh_src = vh_base + (size_t)kt * BKA * DD;
        const __nv_bfloat16* vl_src = vl_base + (size_t)kt * BKA * DD;
#pragma unroll
        for (int j = 0; j < 4; j++) {
            int slot = tid + j * 256;
            int row = slot >> 4;
            int c8 = (slot & 15) << 3;
            *(uint4*)(sKh + row * KSTR + c8) = *(const uint4*)(kh_src + (size_t)row * DD + c8);
            *(uint4*)(sKl + row * KSTR + c8) = *(const uint4*)(kl_src + (size_t)row * DD + c8);
            *(uint4*)(sVh + row * KSTR + c8) = *(const uint4*)(vh_src + (size_t)row * DD + c8);
            *(uint4*)(sVl + row * KSTR + c8) = *(const uint4*)(vl_src + (size_t)row * DD + c8);
        }
        __syncthreads();

        // ---- S = Q K^T (scaled; scale folded into Q) ----
        float s[8][4];
#pragma unroll
        for (int nt = 0; nt < 8; nt++)
#pragma unroll
            for (int e = 0; e < 4; e++) s[nt][e] = 0.f;

#pragma unroll
        for (int ks = 0; ks < 8; ks++) {
#pragma unroll
            for (int p = 0; p < 4; p++) {
                int krow = p * 16 + (lane & 7) + ((lane >> 4) << 3);
                int kcol = ks * 16 + (((lane >> 3) & 1) << 3);
                uint32_t bh[4], bl[4];
                ldsm_x4(bh[0], bh[1], bh[2], bh[3], uKh + (krow * KSTR + kcol) * 2);
                ldsm_x4(bl[0], bl[1], bl[2], bl[3], uKl + (krow * KSTR + kcol) * 2);
                mma16816(s[2 * p],     qfh[ks], bh + 0);
                mma16816(s[2 * p],     qfh[ks], bl + 0);
                mma16816(s[2 * p],     qfl[ks], bh + 0);
                mma16816(s[2 * p + 1], qfh[ks], bh + 2);
                mma16816(s[2 * p + 1], qfh[ks], bl + 2);
                mma16816(s[2 * p + 1], qfl[ks], bh + 2);
            }
        }

        // ---- online softmax (rows g and g+8 of warp tile) ----
        float cm0 = -1e30f, cm1 = -1e30f;
#pragma unroll
        for (int nt = 0; nt < 8; nt++) {
            cm0 = fmaxf(cm0, fmaxf(s[nt][0], s[nt][1]));
            cm1 = fmaxf(cm1, fmaxf(s[nt][2], s[nt][3]));
        }
        cm0 = fmaxf(cm0, __shfl_xor_sync(0xffffffffu, cm0, 1));
        cm0 = fmaxf(cm0, __shfl_xor_sync(0xffffffffu, cm0, 2));
        cm1 = fmaxf(cm1, __shfl_xor_sync(0xffffffffu, cm1, 1));
        cm1 = fmaxf(cm1, __shfl_xor_sync(0xffffffffu, cm1, 2));
        float mn0 = fmaxf(m0, cm0), mn1 = fmaxf(m1, cm1);
        float alpha0 = __expf(m0 - mn0), alpha1 = __expf(m1 - mn1);
        float ls0 = 0.f, ls1 = 0.f;
#pragma unroll
        for (int nt = 0; nt < 8; nt++) {
            s[nt][0] = __expf(s[nt][0] - mn0);
            s[nt][1] = __expf(s[nt][1] - mn0);
            s[nt][2] = __expf(s[nt][2] - mn1);
            s[nt][3] = __expf(s[nt][3] - mn1);
            ls0 += s[nt][0] + s[nt][1];
            ls1 += s[nt][2] + s[nt][3];
        }
        ls0 += __shfl_xor_sync(0xffffffffu, ls0, 1);
        ls0 += __shfl_xor_sync(0xffffffffu, ls0, 2);
        ls1 += __shfl_xor_sync(0xffffffffu, ls1, 1);
        ls1 += __shfl_xor_sync(0xffffffffu, ls1, 2);
        l0 = l0 * alpha0 + ls0;
        l1 = l1 * alpha1 + ls1;
        m0 = mn0; m1 = mn1;
#pragma unroll
        for (int nt = 0; nt < 16; nt++) {
            oacc[nt][0] *= alpha0; oacc[nt][1] *= alpha0;
            oacc[nt][2] *= alpha1; oacc[nt][3] *= alpha1;
        }

        // ---- P -> bf16 hi/lo A-fragments (4 k-steps over 64 keys) ----
        uint32_t pah[4][4], pal[4][4];
#pragma unroll
        for (int s4 = 0; s4 < 4; s4++) {
            float c0 = s[2 * s4][0],     c1 = s[2 * s4][1];
            float c2 = s[2 * s4][2],     c3 = s[2 * s4][3];
            float d0 = s[2 * s4 + 1][0], d1 = s[2 * s4 + 1][1];
            float d2 = s[2 * s4 + 1][2], d3 = s[2 * s4 + 1][3];
            float h;
            pah[s4][0] = pack_bf2(c0, c1);
            pah[s4][1] = pack_bf2(c2, c3);
            pah[s4][2] = pack_bf2(d0, d1);
            pah[s4][3] = pack_bf2(d2, d3);
            h = __bfloat162float(__float2bfloat16(c0)); c0 -= h;
            h = __bfloat162float(__float2bfloat16(c1)); c1 -= h;
            h = __bfloat162float(__float2bfloat16(c2)); c2 -= h;
            h = __bfloat162float(__float2bfloat16(c3)); c3 -= h;
            h = __bfloat162float(__float2bfloat16(d0)); d0 -= h;
            h = __bfloat162float(__float2bfloat16(d1)); d1 -= h;
            h = __bfloat162float(__float2bfloat16(d2)); d2 -= h;
            h = __bfloat162float(__float2bfloat16(d3)); d3 -= h;
            pal[s4][0] = pack_bf2(c0, c1);
            pal[s4][1] = pack_bf2(c2, c3);
            pal[s4][2] = pack_bf2(d0, d1);
            pal[s4][3] = pack_bf2(d2, d3);
        }

        // ---- O += P V  (V B-frags via ldmatrix.trans) ----
#pragma unroll
        for (int p = 0; p < 8; p++) {
#pragma unroll
            for (int s4 = 0; s4 < 4; s4++) {
                int krow = s4 * 16 + (lane & 15);
                int dcol = p * 16 + ((lane >> 4) << 3);
                uint32_t bh[4], bl[4];
                ldsm_x4_t(bh[0], bh[1], bh[2], bh[3], uVh + (krow * KSTR + dcol) * 2);
                ldsm_x4_t(bl[0], bl[1], bl[2], bl[3], uVl + (krow * KSTR + dcol) * 2);
                mma16816(oacc[2 * p],     pah[s4], bh + 0);
                mma16816(oacc[2 * p],     pah[s4], bl + 0);
                mma16816(oacc[2 * p],     pal[s4], bh + 0);
                mma16816(oacc[2 * p + 1], pah[s4], bh + 2);
                mma16816(oacc[2 * p + 1], pah[s4], bl + 2);
                mma16816(oacc[2 * p + 1], pal[s4], bh + 2);
            }
        }
        __syncthreads();
    }

    // ---- epilogue: normalize, split hi/lo, store to Wo-GEMM A buffers -------
    float inv0 = 1.0f / l0, inv1 = 1.0f / l1;
    int t0 = qt * BQA + row0 + g;
#pragma unroll
    for (int nt = 0; nt < 16; nt++) {
        int d = nt * 8 + 2 * tg;
        float o0 = oacc[nt][0] * inv0, o1 = oacc[nt][1] * inv0;
        float o2 = oacc[nt][2] * inv1, o3 = oacc[nt][3] * inv1;
        size_t i0 = ((size_t)b * TT + t0) * KDIM + (size_t)h * DD + d;
        size_t i1 = ((size_t)b * TT + t0 + 8) * KDIM + (size_t)h * DD + d;
        float h0 = __bfloat162float(__float2bfloat16(o0));
        float h1 = __bfloat162float(__float2bfloat16(o1));
        float h2 = __bfloat162float(__float2bfloat16(o2));
        float h3 = __bfloat162float(__float2bfloat16(o3));
        *(uint32_t*)(Ohi + i0) = pack_bf2(o0, o1);
        *(uint32_t*)(Olo + i0) = pack_bf2(o0 - h0, o1 - h1);
        *(uint32_t*)(Ohi + i1) = pack_bf2(o2, o3);
        *(uint32_t*)(Olo + i1) = pack_bf2(o2 - h2, o3 - h3);
    }
}

// ---------------- launch ------------------------------------------------------
extern "C" void kernel_launch(void* const* d_in, const int* in_sizes, int n_in,
                              void* d_out, int out_size) {
    const float* hidden = (const float*)d_in[0];  // [B,T,HID]
    const float* Wqkv   = (const float*)d_in[1];  // [QKV_OUT, HID]
    const float* Wo     = (const float*)d_in[2];  // [HID, H*D]
    const float* qw     = (const float*)d_in[3];  // [H, D]
    const float* kw     = (const float*)d_in[4];  // [KV, D]
    float* out = (float*)d_out;                   // [B,T,HID]

    float* qkv;
    __nv_bfloat16 *ahi, *alo, *bhi, *blo, *qh, *ql, *kh, *kl, *vh, *vl;
    cudaGetSymbolAddress((void**)&qkv, g_qkv);
    cudaGetSymbolAddress((void**)&ahi, g_ahi);
    cudaGetSymbolAddress((void**)&alo, g_alo);
    cudaGetSymbolAddress((void**)&bhi, g_bhi);
    cudaGetSymbolAddress((void**)&blo, g_blo);
    cudaGetSymbolAddress((void**)&qh,  g_qh);
    cudaGetSymbolAddress((void**)&ql,  g_ql);
    cudaGetSymbolAddress((void**)&kh,  g_kh);
    cudaGetSymbolAddress((void**)&kl,  g_kl);
    cudaGetSymbolAddress((void**)&vh,  g_vh);
    cudaGetSymbolAddress((void**)&vl,  g_vl);

    cudaFuncSetAttribute(attn_hmma, cudaFuncAttributeMaxDynamicSharedMemorySize,
                         ATT_SMEM);

    // 1) convert inputs to bf16 hi/lo
    cvt_hilo<<<1024, 256>>>(hidden, ahi, alo, (size_t)MT * KDIM);
    cvt_hilo<<<1024, 256>>>(Wqkv, bhi, blo, (size_t)QKV_OUT * KDIM);

    // 2) QKV projection
    {
        dim3 grid(QKV_OUT / 128, MT / 128);
        hmma_gemm<<<grid, 256>>>(ahi, alo, bhi, blo, qkv, QKV_OUT);
    }

    // 3) norm scalar + RoPE -> bf16 hi/lo Q/K/V
    {
        dim3 grid(MT, HH + 2 * KVH);
        norm_rope_kernel<<<grid, DD>>>(qkv, qw, kw, qh, ql, kh, kl, vh, vl);
    }

    // 4) Attention (HMMA) -> writes hi/lo directly into Wo-GEMM A buffers
    {
        dim3 grid(TT / BQA, HH, BB);
        attn_hmma<<<grid, 256, ATT_SMEM>>>(qh, ql, kh, kl, vh, vl, ahi, alo);
    }

    // 5) Output projection
    cvt_hilo<<<1024, 256>>>(Wo, bhi, blo, (size_t)HID * KDIM);
    {
        dim3 grid(HID / 128, MT / 128);
        hmma_gemm<<<grid, 256>>>(ahi, alo, bhi, blo, out, HID);
    }
}

// round 13
// speedup vs baseline: 2.1265x; 1.1023x over previous
#include <cuda_runtime.h>
#include <cuda_bf16.h>
#include <math.h>
#include <stdint.h>

// Problem constants
#define BB 2
#define TT 2048
#define HID 4096
#define HH 32
#define KVH 4
#define DD 128
#define GROUP 8
#define QKV_OUT ((HH + 2*KVH)*DD)   // 5120
#define MT (BB*TT)                  // 4096
#define KDIM 4096                   // K for both big GEMMs
#define SCALE_F 0.08838834764831845f

// ---------------- scratch (device globals; no allocations allowed) ------------
__device__ float g_qkv[(size_t)MT * QKV_OUT];     // 4096 x 5120 fp32

// bf16 hi/lo split buffers for tensor-core GEMMs
__device__ __nv_bfloat16 g_ahi[(size_t)MT * KDIM];
__device__ __nv_bfloat16 g_alo[(size_t)MT * KDIM];
__device__ __nv_bfloat16 g_bhi[(size_t)QKV_OUT * KDIM];
__device__ __nv_bfloat16 g_blo[(size_t)QKV_OUT * KDIM];

// bf16 hi/lo Q/K/V for attention ([b,h,t,d] / [b,kv,t,d])
__device__ __nv_bfloat16 g_qh[(size_t)BB * HH * TT * DD];
__device__ __nv_bfloat16 g_ql[(size_t)BB * HH * TT * DD];
__device__ __nv_bfloat16 g_kh[(size_t)BB * KVH * TT * DD];
__device__ __nv_bfloat16 g_kl[(size_t)BB * KVH * TT * DD];
__device__ __nv_bfloat16 g_vh[(size_t)BB * KVH * TT * DD];
__device__ __nv_bfloat16 g_vl[(size_t)BB * KVH * TT * DD];

// ================= helpers ===================================================
__device__ __forceinline__ void mma16816(float* c, const uint32_t* a, const uint32_t* b) {
    asm volatile("mma.sync.aligned.m16n8k16.row.col.f32.bf16.bf16.f32 "
                 "{%0,%1,%2,%3}, {%4,%5,%6,%7}, {%8,%9}, {%0,%1,%2,%3};"
                 : "+f"(c[0]), "+f"(c[1]), "+f"(c[2]), "+f"(c[3])
                 : "r"(a[0]), "r"(a[1]), "r"(a[2]), "r"(a[3]),
                   "r"(b[0]), "r"(b[1]));
}
__device__ __forceinline__ void ldsm_x4(uint32_t& r0, uint32_t& r1, uint32_t& r2,
                                        uint32_t& r3, uint32_t addr) {
    asm volatile("ldmatrix.sync.aligned.m8n8.x4.shared.b16 {%0,%1,%2,%3}, [%4];"
                 : "=r"(r0), "=r"(r1), "=r"(r2), "=r"(r3) : "r"(addr));
}
__device__ __forceinline__ void ldsm_x4_t(uint32_t& r0, uint32_t& r1, uint32_t& r2,
                                          uint32_t& r3, uint32_t addr) {
    asm volatile("ldmatrix.sync.aligned.m8n8.x4.trans.shared.b16 {%0,%1,%2,%3}, [%4];"
                 : "=r"(r0), "=r"(r1), "=r"(r2), "=r"(r3) : "r"(addr));
}
__device__ __forceinline__ uint32_t smem_u32(const void* p) {
    uint32_t a;
    asm("{ .reg .u64 t; cvta.to.shared.u64 t, %1; cvt.u32.u64 %0, t; }"
        : "=r"(a) : "l"(p));
    return a;
}
__device__ __forceinline__ uint32_t pack_bf2(float x, float y) {
    __nv_bfloat162 h = __floats2bfloat162_rn(x, y);
    return *(uint32_t*)&h;
}
__device__ __forceinline__ void cp16(void* smem_dst, const void* gsrc) {
    uint32_t d = smem_u32(smem_dst);
    asm volatile("cp.async.cg.shared.global [%0], [%1], 16;" :: "r"(d), "l"(gsrc));
}
#define CP_COMMIT() asm volatile("cp.async.commit_group;" ::: "memory")
#define CP_WAIT1()  asm volatile("cp.async.wait_group 1;" ::: "memory")
#define CP_WAIT0()  asm volatile("cp.async.wait_group 0;" ::: "memory")

// ================= hi/lo conversion ==========================================
__global__ void cvt_hilo(const float* __restrict__ src,
                         __nv_bfloat16* __restrict__ hi,
                         __nv_bfloat16* __restrict__ lo, size_t n) {
    size_t i = (size_t)blockIdx.x * blockDim.x + threadIdx.x;
    size_t stride = (size_t)gridDim.x * blockDim.x;
    for (; i < n / 4; i += stride) {
        float4 x = ((const float4*)src)[i];
        __nv_bfloat16 h0 = __float2bfloat16(x.x);
        __nv_bfloat16 h1 = __float2bfloat16(x.y);
        __nv_bfloat16 h2 = __float2bfloat16(x.z);
        __nv_bfloat16 h3 = __float2bfloat16(x.w);
        __nv_bfloat16 l0 = __float2bfloat16(x.x - __bfloat162float(h0));
        __nv_bfloat16 l1 = __float2bfloat16(x.y - __bfloat162float(h1));
        __nv_bfloat16 l2 = __float2bfloat16(x.z - __bfloat162float(h2));
        __nv_bfloat16 l3 = __float2bfloat16(x.w - __bfloat162float(h3));
        __nv_bfloat162 hp0, hp1, lp0, lp1;
        hp0.x = h0; hp0.y = h1; hp1.x = h2; hp1.y = h3;
        lp0.x = l0; lp0.y = l1; lp1.x = l2; lp1.y = l3;
        ((__nv_bfloat162*)hi)[i * 2 + 0] = hp0;
        ((__nv_bfloat162*)hi)[i * 2 + 1] = hp1;
        ((__nv_bfloat162*)lo)[i * 2 + 0] = lp0;
        ((__nv_bfloat162*)lo)[i * 2 + 1] = lp1;
    }
}

// ================= HMMA GEMM (cp.async 2-stage): C = A * B^T =================
#define GBK2 32
#define SSTR 40
#define GTILE (128 * SSTR)               // bf16 elems per tile
#define GSTAGE (4 * GTILE)               // elems per stage (Ah,Al,Bh,Bl)
#define GEMM_SMEM (2 * GSTAGE * 2)       // bytes (2 stages)

__global__ __launch_bounds__(256) void hmma_gemm(const __nv_bfloat16* __restrict__ Ah,
                                                 const __nv_bfloat16* __restrict__ Al,
                                                 const __nv_bfloat16* __restrict__ Bh,
                                                 const __nv_bfloat16* __restrict__ Bl,
                                                 float* __restrict__ C, int N) {
    extern __shared__ __nv_bfloat16 smg[];

    const int tid  = threadIdx.x;
    const int lane = tid & 31;
    const int warp = tid >> 5;
    const int wm = (warp & 1) * 64;
    const int wn = (warp >> 1) * 32;
    const int g  = lane >> 2;
    const int tg = lane & 3;

    const int bm = blockIdx.y * 128;
    const int bn = blockIdx.x * 128;

    const __nv_bfloat16* gsrc[4];
    gsrc[0] = Ah + (size_t)bm * KDIM;
    gsrc[1] = Al + (size_t)bm * KDIM;
    gsrc[2] = Bh + (size_t)bn * KDIM;
    gsrc[3] = Bl + (size_t)bn * KDIM;

    // staging indices (each thread moves 2x16B per tile)
    const int row_st = tid >> 2;
    const int c8_st  = (tid & 3) * 8;

    float acc[4][4][4];
#pragma unroll
    for (int mt = 0; mt < 4; mt++)
#pragma unroll
        for (int nt = 0; nt < 4; nt++)
#pragma unroll
            for (int e = 0; e < 4; e++) acc[mt][nt][e] = 0.f;

    const int NCH = KDIM / GBK2;

    // prefetch chunk 0 -> stage 0
#pragma unroll
    for (int t = 0; t < 4; t++) {
        __nv_bfloat16* st = smg + t * GTILE;
#pragma unroll
        for (int j = 0; j < 2; j++) {
            int row = row_st + j * 64;
            cp16(st + row * SSTR + c8_st, gsrc[t] + (size_t)row * KDIM + c8_st);
        }
    }
    CP_COMMIT();

    for (int k = 0; k < NCH; k++) {
        // prefetch chunk k+1 into the other stage
        if (k + 1 < NCH) {
            const int k0n = (k + 1) * GBK2;
            __nv_bfloat16* stage = smg + ((k + 1) & 1) * GSTAGE;
#pragma unroll
            for (int t = 0; t < 4; t++) {
                __nv_bfloat16* st = stage + t * GTILE;
#pragma unroll
                for (int j = 0; j < 2; j++) {
                    int row = row_st + j * 64;
                    cp16(st + row * SSTR + c8_st,
                         gsrc[t] + (size_t)row * KDIM + k0n + c8_st);
                }
            }
            CP_COMMIT();
            CP_WAIT1();
        } else {
            CP_WAIT0();
        }
        __syncthreads();

        const __nv_bfloat16* sAh = smg + (k & 1) * GSTAGE;
        const __nv_bfloat16* sAl = sAh + GTILE;
        const __nv_bfloat16* sBh = sAl + GTILE;
        const __nv_bfloat16* sBl = sBh + GTILE;

#pragma unroll
        for (int ks = 0; ks < 2; ks++) {
            const int kk = ks * 16;
            uint32_t ah[4][4], al[4][4], bh[4][2], bl[4][2];
#pragma unroll
            for (int mt = 0; mt < 4; mt++) {
                int r = wm + mt * 16 + g;
                const __nv_bfloat16* p0 = sAh + r * SSTR + kk + tg * 2;
                const __nv_bfloat16* p1 = sAh + (r + 8) * SSTR + kk + tg * 2;
                ah[mt][0] = *(const uint32_t*)(p0);
                ah[mt][1] = *(const uint32_t*)(p1);
                ah[mt][2] = *(const uint32_t*)(p0 + 8);
                ah[mt][3] = *(const uint32_t*)(p1 + 8);
                const __nv_bfloat16* q0 = sAl + r * SSTR + kk + tg * 2;
                const __nv_bfloat16* q1 = sAl + (r + 8) * SSTR + kk + tg * 2;
                al[mt][0] = *(const uint32_t*)(q0);
                al[mt][1] = *(const uint32_t*)(q1);
                al[mt][2] = *(const uint32_t*)(q0 + 8);
                al[mt][3] = *(const uint32_t*)(q1 + 8);
            }
#pragma unroll
            for (int nt = 0; nt < 4; nt++) {
                int rb = wn + nt * 8 + g;
                const __nv_bfloat16* p = sBh + rb * SSTR + kk + tg * 2;
                bh[nt][0] = *(const uint32_t*)(p);
                bh[nt][1] = *(const uint32_t*)(p + 8);
                const __nv_bfloat16* q = sBl + rb * SSTR + kk + tg * 2;
                bl[nt][0] = *(const uint32_t*)(q);
                bl[nt][1] = *(const uint32_t*)(q + 8);
            }
#pragma unroll
            for (int mt = 0; mt < 4; mt++)
#pragma unroll
                for (int nt = 0; nt < 4; nt++) {
                    mma16816(acc[mt][nt], ah[mt], bh[nt]);
                    mma16816(acc[mt][nt], ah[mt], bl[nt]);
                    mma16816(acc[mt][nt], al[mt], bh[nt]);
                }
        }
        __syncthreads();
    }

#pragma unroll
    for (int mt = 0; mt < 4; mt++) {
#pragma unroll
        for (int nt = 0; nt < 4; nt++) {
            int row = bm + wm + mt * 16 + g;
            int col = bn + wn + nt * 8 + tg * 2;
            *(float2*)(C + (size_t)row * N + col) =
                make_float2(acc[mt][nt][0], acc[mt][nt][1]);
            *(float2*)(C + (size_t)(row + 8) * N + col) =
                make_float2(acc[mt][nt][2], acc[mt][nt][3]);
        }
    }
}

// ---------------- "RMSNorm" (reference semantics) + RoPE -> bf16 hi/lo -------
__global__ void norm_rope_kernel(const float* __restrict__ qkv,
                                 const float* __restrict__ qw,
                                 const float* __restrict__ kw,
                                 __nv_bfloat16* __restrict__ Qh,
                                 __nv_bfloat16* __restrict__ Ql,
                                 __nv_bfloat16* __restrict__ Kh,
                                 __nv_bfloat16* __restrict__ Kl,
                                 __nv_bfloat16* __restrict__ Vh,
                                 __nv_bfloat16* __restrict__ Vl) {
    const int m = blockIdx.x;
    const int hy = blockIdx.y;
    const int b = m / TT, t = m % TT;
    const int d = threadIdx.x;

    const float* src = qkv + (size_t)m * QKV_OUT + (size_t)hy * DD;
    float x = src[d];

    __shared__ float sh[DD];
    __shared__ float red[4];

    if (hy < HH + KVH) {
        float ss = x * x;
#pragma unroll
        for (int o = 16; o; o >>= 1) ss += __shfl_xor_sync(0xffffffffu, ss, o);
        if ((d & 31) == 0) red[d >> 5] = ss;
        __syncthreads();
        float tot = red[0] + red[1] + red[2] + red[3];
        float r = rsqrtf(tot * (1.0f / DD) + 1e-6f);
        float w = (hy < HH) ? qw[hy * DD + d] : kw[(hy - HH) * DD + d];
        sh[d] = r * w;
        __syncthreads();
        int i = d & 63;
        double invf = exp(-(double)i / 64.0 * log(10000.0));
        double th = (double)t * invf;
        float c = (float)cos(th);
        float s = (float)sin(th);
        float x1 = sh[i], x2 = sh[i + 64];
        float out = (d < 64) ? (x1 * c - x2 * s) : (x1 * s + x2 * c);
        if (hy < HH) {
            out *= SCALE_F;
            __nv_bfloat16 hv = __float2bfloat16(out);
            size_t idx = (((size_t)b * HH + hy) * TT + t) * DD + d;
            Qh[idx] = hv;
            Ql[idx] = __float2bfloat16(out - __bfloat162float(hv));
        } else {
            __nv_bfloat16 hv = __float2bfloat16(out);
            size_t idx = (((size_t)b * KVH + (hy - HH)) * TT + t) * DD + d;
            Kh[idx] = hv;
            Kl[idx] = __float2bfloat16(out - __bfloat162float(hv));
        }
    } else {
        int vh = hy - HH - KVH;
        __nv_bfloat16 hv = __float2bfloat16(x);
        size_t idx = (((size_t)b * KVH + vh) * TT + t) * DD + d;
        Vh[idx] = hv;
        Vl[idx] = __float2bfloat16(x - __bfloat162float(hv));
    }
}

// ---------------- Flash attention (HMMA, cp.async 2-stage) -------------------
#define BQA 128
#define BKA 64
#define KSTR 136
#define ATILE (BKA * KSTR)               // bf16 elems per tile
#define ASTAGE (4 * ATILE)               // Kh,Kl,Vh,Vl
#define ATT_SMEM (2 * ASTAGE * 2)        // bytes (2 stages)

__global__ __launch_bounds__(256) void attn_hmma(
    const __nv_bfloat16* __restrict__ Qh_, const __nv_bfloat16* __restrict__ Ql_,
    const __nv_bfloat16* __restrict__ Kh_, const __nv_bfloat16* __restrict__ Kl_,
    const __nv_bfloat16* __restrict__ Vh_, const __nv_bfloat16* __restrict__ Vl_,
    __nv_bfloat16* __restrict__ Ohi, __nv_bfloat16* __restrict__ Olo) {
    extern __shared__ __nv_bfloat16 smn[];

    const int tid  = threadIdx.x;
    const int lane = tid & 31;
    const int warp = tid >> 5;
    const int g  = lane >> 2;
    const int tg = lane & 3;

    const int qt = blockIdx.x, h = blockIdx.y, b = blockIdx.z;
    const int kvh = h / GROUP;
    const int row0 = warp * 16;

    const __nv_bfloat16* qh_base = Qh_ + (((size_t)b * HH + h) * TT + (size_t)qt * BQA) * DD;
    const __nv_bfloat16* ql_base = Ql_ + (((size_t)b * HH + h) * TT + (size_t)qt * BQA) * DD;
    const __nv_bfloat16* gsrc[4];
    gsrc[0] = Kh_ + ((size_t)b * KVH + kvh) * TT * DD;
    gsrc[1] = Kl_ + ((size_t)b * KVH + kvh) * TT * DD;
    gsrc[2] = Vh_ + ((size_t)b * KVH + kvh) * TT * DD;
    gsrc[3] = Vl_ + ((size_t)b * KVH + kvh) * TT * DD;

    // staging indices: each thread moves 1x16B per tile per j (4 j-iters)
    const int row_st = tid >> 4;          // 0..15
    const int c8_st  = (tid & 15) << 3;   // 0..120

    // preload Q A-fragments
    uint32_t qfh[8][4], qfl[8][4];
#pragma unroll
    for (int ks = 0; ks < 8; ks++) {
        int d0 = ks * 16;
        const __nv_bfloat16* r0p = qh_base + (size_t)(row0 + g) * DD + d0 + 2 * tg;
        const __nv_bfloat16* r1p = qh_base + (size_t)(row0 + g + 8) * DD + d0 + 2 * tg;
        qfh[ks][0] = *(const uint32_t*)(r0p);
        qfh[ks][1] = *(const uint32_t*)(r1p);
        qfh[ks][2] = *(const uint32_t*)(r0p + 8);
        qfh[ks][3] = *(const uint32_t*)(r1p + 8);
        const __nv_bfloat16* s0p = ql_base + (size_t)(row0 + g) * DD + d0 + 2 * tg;
        const __nv_bfloat16* s1p = ql_base + (size_t)(row0 + g + 8) * DD + d0 + 2 * tg;
        qfl[ks][0] = *(const uint32_t*)(s0p);
        qfl[ks][1] = *(const uint32_t*)(s1p);
        qfl[ks][2] = *(const uint32_t*)(s0p + 8);
        qfl[ks][3] = *(const uint32_t*)(s1p + 8);
    }

    float oacc[16][4];
#pragma unroll
    for (int nt = 0; nt < 16; nt++)
#pragma unroll
        for (int e = 0; e < 4; e++) oacc[nt][e] = 0.f;
    float m0 = -1e30f, m1 = -1e30f, l0 = 0.f, l1 = 0.f;

    const int NKT = TT / BKA;

    // prefetch chunk 0 -> stage 0
#pragma unroll
    for (int t = 0; t < 4; t++) {
        __nv_bfloat16* st = smn + t * ATILE;
#pragma unroll
        for (int j = 0; j < 4; j++) {
            int row = row_st + j * 16;
            cp16(st + row * KSTR + c8_st, gsrc[t] + (size_t)row * DD + c8_st);
        }
    }
    CP_COMMIT();

    for (int kt = 0; kt < NKT; kt++) {
        if (kt + 1 < NKT) {
            __nv_bfloat16* stage = smn + ((kt + 1) & 1) * ASTAGE;
            const size_t goff = (size_t)(kt + 1) * BKA * DD;
#pragma unroll
            for (int t = 0; t < 4; t++) {
                __nv_bfloat16* st = stage + t * ATILE;
#pragma unroll
                for (int j = 0; j < 4; j++) {
                    int row = row_st + j * 16;
                    cp16(st + row * KSTR + c8_st,
                         gsrc[t] + goff + (size_t)row * DD + c8_st);
                }
            }
            CP_COMMIT();
            CP_WAIT1();
        } else {
            CP_WAIT0();
        }
        __syncthreads();

        const __nv_bfloat16* sKh = smn + (kt & 1) * ASTAGE;
        const uint32_t uKh = smem_u32(sKh);
        const uint32_t uKl = uKh + ATILE * 2;
        const uint32_t uVh = uKl + ATILE * 2;
        const uint32_t uVl = uVh + ATILE * 2;

        // ---- S = Q K^T ----
        float s[8][4];
#pragma unroll
        for (int nt = 0; nt < 8; nt++)
#pragma unroll
            for (int e = 0; e < 4; e++) s[nt][e] = 0.f;

#pragma unroll
        for (int ks = 0; ks < 8; ks++) {
#pragma unroll
            for (int p = 0; p < 4; p++) {
                int krow = p * 16 + (lane & 7) + ((lane >> 4) << 3);
                int kcol = ks * 16 + (((lane >> 3) & 1) << 3);
                uint32_t bh[4], bl[4];
                ldsm_x4(bh[0], bh[1], bh[2], bh[3], uKh + (krow * KSTR + kcol) * 2);
                ldsm_x4(bl[0], bl[1], bl[2], bl[3], uKl + (krow * KSTR + kcol) * 2);
                mma16816(s[2 * p],     qfh[ks], bh + 0);
                mma16816(s[2 * p],     qfh[ks], bl + 0);
                mma16816(s[2 * p],     qfl[ks], bh + 0);
                mma16816(s[2 * p + 1], qfh[ks], bh + 2);
                mma16816(s[2 * p + 1], qfh[ks], bl + 2);
                mma16816(s[2 * p + 1], qfl[ks], bh + 2);
            }
        }

        // ---- online softmax ----
        float cm0 = -1e30f, cm1 = -1e30f;
#pragma unroll
        for (int nt = 0; nt < 8; nt++) {
            cm0 = fmaxf(cm0, fmaxf(s[nt][0], s[nt][1]));
            cm1 = fmaxf(cm1, fmaxf(s[nt][2], s[nt][3]));
        }
        cm0 = fmaxf(cm0, __shfl_xor_sync(0xffffffffu, cm0, 1));
        cm0 = fmaxf(cm0, __shfl_xor_sync(0xffffffffu, cm0, 2));
        cm1 = fmaxf(cm1, __shfl_xor_sync(0xffffffffu, cm1, 1));
        cm1 = fmaxf(cm1, __shfl_xor_sync(0xffffffffu, cm1, 2));
        float mn0 = fmaxf(m0, cm0), mn1 = fmaxf(m1, cm1);
        float alpha0 = __expf(m0 - mn0), alpha1 = __expf(m1 - mn1);
        float ls0 = 0.f, ls1 = 0.f;
#pragma unroll
        for (int nt = 0; nt < 8; nt++) {
            s[nt][0] = __expf(s[nt][0] - mn0);
            s[nt][1] = __expf(s[nt][1] - mn0);
            s[nt][2] = __expf(s[nt][2] - mn1);
            s[nt][3] = __expf(s[nt][3] - mn1);
            ls0 += s[nt][0] + s[nt][1];
            ls1 += s[nt][2] + s[nt][3];
        }
        ls0 += __shfl_xor_sync(0xffffffffu, ls0, 1);
        ls0 += __shfl_xor_sync(0xffffffffu, ls0, 2);
        ls1 += __shfl_xor_sync(0xffffffffu, ls1, 1);
        ls1 += __shfl_xor_sync(0xffffffffu, ls1, 2);
        l0 = l0 * alpha0 + ls0;
        l1 = l1 * alpha1 + ls1;
        m0 = mn0; m1 = mn1;
#pragma unroll
        for (int nt = 0; nt < 16; nt++) {
            oacc[nt][0] *= alpha0; oacc[nt][1] *= alpha0;
            oacc[nt][2] *= alpha1; oacc[nt][3] *= alpha1;
        }

        // ---- P -> bf16 hi/lo A-fragments ----
        uint32_t pah[4][4], pal[4][4];
#pragma unroll
        for (int s4 = 0; s4 < 4; s4++) {
            float c0 = s[2 * s4][0],     c1 = s[2 * s4][1];
            float c2 = s[2 * s4][2],     c3 = s[2 * s4][3];
            float d0 = s[2 * s4 + 1][0], d1 = s[2 * s4 + 1][1];
            float d2 = s[2 * s4 + 1][2], d3 = s[2 * s4 + 1][3];
            float hh;
            pah[s4][0] = pack_bf2(c0, c1);
            pah[s4][1] = pack_bf2(c2, c3);
            pah[s4][2] = pack_bf2(d0, d1);
            pah[s4][3] = pack_bf2(d2, d3);
            hh = __bfloat162float(__float2bfloat16(c0)); c0 -= hh;
            hh = __bfloat162float(__float2bfloat16(c1)); c1 -= hh;
            hh = __bfloat162float(__float2bfloat16(c2)); c2 -= hh;
            hh = __bfloat162float(__float2bfloat16(c3)); c3 -= hh;
            hh = __bfloat162float(__float2bfloat16(d0)); d0 -= hh;
            hh = __bfloat162float(__float2bfloat16(d1)); d1 -= hh;
            hh = __bfloat162float(__float2bfloat16(d2)); d2 -= hh;
            hh = __bfloat162float(__float2bfloat16(d3)); d3 -= hh;
            pal[s4][0] = pack_bf2(c0, c1);
            pal[s4][1] = pack_bf2(c2, c3);
            pal[s4][2] = pack_bf2(d0, d1);
            pal[s4][3] = pack_bf2(d2, d3);
        }

        // ---- O += P V ----
#pragma unroll
        for (int p = 0; p < 8; p++) {
#pragma unroll
            for (int s4 = 0; s4 < 4; s4++) {
                int krow = s4 * 16 + (lane & 15);
                int dcol = p * 16 + ((lane >> 4) << 3);
                uint32_t bh[4], bl[4];
                ldsm_x4_t(bh[0], bh[1], bh[2], bh[3], uVh + (krow * KSTR + dcol) * 2);
                ldsm_x4_t(bl[0], bl[1], bl[2], bl[3], uVl + (krow * KSTR + dcol) * 2);
                mma16816(oacc[2 * p],     pah[s4], bh + 0);
                mma16816(oacc[2 * p],     pah[s4], bl + 0);
                mma16816(oacc[2 * p],     pal[s4], bh + 0);
                mma16816(oacc[2 * p + 1], pah[s4], bh + 2);
                mma16816(oacc[2 * p + 1], pah[s4], bl + 2);
                mma16816(oacc[2 * p + 1], pal[s4], bh + 2);
            }
        }
        __syncthreads();
    }

    // ---- epilogue ----
    float inv0 = 1.0f / l0, inv1 = 1.0f / l1;
    int t0 = qt * BQA + row0 + g;
#pragma unroll
    for (int nt = 0; nt < 16; nt++) {
        int d = nt * 8 + 2 * tg;
        float o0 = oacc[nt][0] * inv0, o1 = oacc[nt][1] * inv0;
        float o2 = oacc[nt][2] * inv1, o3 = oacc[nt][3] * inv1;
        size_t i0 = ((size_t)b * TT + t0) * KDIM + (size_t)h * DD + d;
        size_t i1 = ((size_t)b * TT + t0 + 8) * KDIM + (size_t)h * DD + d;
        float h0 = __bfloat162float(__float2bfloat16(o0));
        float h1 = __bfloat162float(__float2bfloat16(o1));
        float h2 = __bfloat162float(__float2bfloat16(o2));
        float h3 = __bfloat162float(__float2bfloat16(o3));
        *(uint32_t*)(Ohi + i0) = pack_bf2(o0, o1);
        *(uint32_t*)(Olo + i0) = pack_bf2(o0 - h0, o1 - h1);
        *(uint32_t*)(Ohi + i1) = pack_bf2(o2, o3);
        *(uint32_t*)(Olo + i1) = pack_bf2(o2 - h2, o3 - h3);
    }
}

// ---------------- launch ------------------------------------------------------
extern "C" void kernel_launch(void* const* d_in, const int* in_sizes, int n_in,
                              void* d_out, int out_size) {
    const float* hidden = (const float*)d_in[0];  // [B,T,HID]
    const float* Wqkv   = (const float*)d_in[1];  // [QKV_OUT, HID]
    const float* Wo     = (const float*)d_in[2];  // [HID, H*D]
    const float* qw     = (const float*)d_in[3];  // [H, D]
    const float* kw     = (const float*)d_in[4];  // [KV, D]
    float* out = (float*)d_out;                   // [B,T,HID]

    float* qkv;
    __nv_bfloat16 *ahi, *alo, *bhi, *blo, *qh, *ql, *kh, *kl, *vh, *vl;
    cudaGetSymbolAddress((void**)&qkv, g_qkv);
    cudaGetSymbolAddress((void**)&ahi, g_ahi);
    cudaGetSymbolAddress((void**)&alo, g_alo);
    cudaGetSymbolAddress((void**)&bhi, g_bhi);
    cudaGetSymbolAddress((void**)&blo, g_blo);
    cudaGetSymbolAddress((void**)&qh,  g_qh);
    cudaGetSymbolAddress((void**)&ql,  g_ql);
    cudaGetSymbolAddress((void**)&kh,  g_kh);
    cudaGetSymbolAddress((void**)&kl,  g_kl);
    cudaGetSymbolAddress((void**)&vh,  g_vh);
    cudaGetSymbolAddress((void**)&vl,  g_vl);

    cudaFuncSetAttribute(attn_hmma, cudaFuncAttributeMaxDynamicSharedMemorySize,
                         ATT_SMEM);
    cudaFuncSetAttribute(hmma_gemm, cudaFuncAttributeMaxDynamicSharedMemorySize,
                         GEMM_SMEM);

    // 1) convert inputs to bf16 hi/lo
    cvt_hilo<<<1024, 256>>>(hidden, ahi, alo, (size_t)MT * KDIM);
    cvt_hilo<<<1024, 256>>>(Wqkv, bhi, blo, (size_t)QKV_OUT * KDIM);

    // 2) QKV projection
    {
        dim3 grid(QKV_OUT / 128, MT / 128);
        hmma_gemm<<<grid, 256, GEMM_SMEM>>>(ahi, alo, bhi, blo, qkv, QKV_OUT);
    }

    // 3) norm scalar + RoPE -> bf16 hi/lo Q/K/V
    {
        dim3 grid(MT, HH + 2 * KVH);
        norm_rope_kernel<<<grid, DD>>>(qkv, qw, kw, qh, ql, kh, kl, vh, vl);
    }

    // 4) Attention (HMMA) -> writes hi/lo directly into Wo-GEMM A buffers
    {
        dim3 grid(TT / BQA, HH, BB);
        attn_hmma<<<grid, 256, ATT_SMEM>>>(qh, ql, kh, kl, vh, vl, ahi, alo);
    }

    // 5) Output projection
    cvt_hilo<<<1024, 256>>>(Wo, bhi, blo, (size_t)HID * KDIM);
    {
        dim3 grid(HID / 128, MT / 128);
        hmma_gemm<<<grid, 256, GEMM_SMEM>>>(ahi, alo, bhi, blo, out, HID);
    }
}

// round 15
// speedup vs baseline: 4.0540x; 1.9064x over previous
#include <cuda_runtime.h>
#include <cuda_bf16.h>
#include <math.h>
#include <stdint.h>

// Problem constants
#define BB 2
#define TT 2048
#define HID 4096
#define HH 32
#define KVH 4
#define DD 128
#define GROUP 8
#define QKV_OUT ((HH + 2*KVH)*DD)   // 5120
#define MT (BB*TT)                  // 4096
#define KDIM 4096
#define SCALE_F 0.08838834764831845f

// ---------------- scratch (device globals; no allocations allowed) ------------
__device__ float g_qkv[(size_t)MT * QKV_OUT];

__device__ __nv_bfloat16 g_ahi[(size_t)MT * KDIM];
__device__ __nv_bfloat16 g_alo[(size_t)MT * KDIM];
__device__ __nv_bfloat16 g_bhi[(size_t)QKV_OUT * KDIM];
__device__ __nv_bfloat16 g_blo[(size_t)QKV_OUT * KDIM];

__device__ __nv_bfloat16 g_vh[(size_t)BB * KVH * TT * DD];
__device__ __nv_bfloat16 g_vl[(size_t)BB * KVH * TT * DD];

__device__ float g_rq[(size_t)BB * HH * TT];    // SCALE * rsqrt(mean q^2 + eps)
__device__ float g_rk[(size_t)BB * KVH * TT];   // rsqrt(mean k^2 + eps)
__device__ float g_G[(size_t)HH * 4096];        // per-head rope kernel table

// ================= helpers ===================================================
__device__ __forceinline__ void mma16816(float* c, const uint32_t* a, const uint32_t* b) {
    asm volatile("mma.sync.aligned.m16n8k16.row.col.f32.bf16.bf16.f32 "
                 "{%0,%1,%2,%3}, {%4,%5,%6,%7}, {%8,%9}, {%0,%1,%2,%3};"
                 : "+f"(c[0]), "+f"(c[1]), "+f"(c[2]), "+f"(c[3])
                 : "r"(a[0]), "r"(a[1]), "r"(a[2]), "r"(a[3]),
                   "r"(b[0]), "r"(b[1]));
}
__device__ __forceinline__ void ldsm_x4_t(uint32_t& r0, uint32_t& r1, uint32_t& r2,
                                          uint32_t& r3, uint32_t addr) {
    asm volatile("ldmatrix.sync.aligned.m8n8.x4.trans.shared.b16 {%0,%1,%2,%3}, [%4];"
                 : "=r"(r0), "=r"(r1), "=r"(r2), "=r"(r3) : "r"(addr));
}
__device__ __forceinline__ uint32_t smem_u32(const void* p) {
    uint32_t a;
    asm("{ .reg .u64 t; cvta.to.shared.u64 t, %1; cvt.u32.u64 %0, t; }"
        : "=r"(a) : "l"(p));
    return a;
}
__device__ __forceinline__ uint32_t pack_bf2(float x, float y) {
    __nv_bfloat162 h = __floats2bfloat162_rn(x, y);
    return *(uint32_t*)&h;
}
__device__ __forceinline__ void cp16(void* smem_dst, const void* gsrc) {
    uint32_t d = smem_u32(smem_dst);
    asm volatile("cp.async.cg.shared.global [%0], [%1], 16;" :: "r"(d), "l"(gsrc));
}
#define CP_COMMIT() asm volatile("cp.async.commit_group;" ::: "memory")
#define CP_WAIT1()  asm volatile("cp.async.wait_group 1;" ::: "memory")
#define CP_WAIT0()  asm volatile("cp.async.wait_group 0;" ::: "memory")

// ================= hi/lo conversion ==========================================
__global__ void cvt_hilo(const float* __restrict__ src,
                         __nv_bfloat16* __restrict__ hi,
                         __nv_bfloat16* __restrict__ lo, size_t n) {
    size_t i = (size_t)blockIdx.x * blockDim.x + threadIdx.x;
    size_t stride = (size_t)gridDim.x * blockDim.x;
    for (; i < n / 4; i += stride) {
        float4 x = ((const float4*)src)[i];
        __nv_bfloat16 h0 = __float2bfloat16(x.x);
        __nv_bfloat16 h1 = __float2bfloat16(x.y);
        __nv_bfloat16 h2 = __float2bfloat16(x.z);
        __nv_bfloat16 h3 = __float2bfloat16(x.w);
        __nv_bfloat16 l0 = __float2bfloat16(x.x - __bfloat162float(h0));
        __nv_bfloat16 l1 = __float2bfloat16(x.y - __bfloat162float(h1));
        __nv_bfloat16 l2 = __float2bfloat16(x.z - __bfloat162float(h2));
        __nv_bfloat16 l3 = __float2bfloat16(x.w - __bfloat162float(h3));
        __nv_bfloat162 hp0, hp1, lp0, lp1;
        hp0.x = h0; hp0.y = h1; hp1.x = h2; hp1.y = h3;
        lp0.x = l0; lp0.y = l1; lp1.x = l2; lp1.y = l3;
        ((__nv_bfloat162*)hi)[i * 2 + 0] = hp0;
        ((__nv_bfloat162*)hi)[i * 2 + 1] = hp1;
        ((__nv_bfloat162*)lo)[i * 2 + 0] = lp0;
        ((__nv_bfloat162*)lo)[i * 2 + 1] = lp1;
    }
}

// ================= HMMA GEMM (cp.async 2-stage): C = A * B^T =================
#define GBK2 32
#define SSTR 40
#define GTILE (128 * SSTR)
#define GSTAGE (4 * GTILE)
#define GEMM_SMEM (2 * GSTAGE * 2)

__global__ __launch_bounds__(256) void hmma_gemm(const __nv_bfloat16* __restrict__ Ah,
                                                 const __nv_bfloat16* __restrict__ Al,
                                                 const __nv_bfloat16* __restrict__ Bh,
                                                 const __nv_bfloat16* __restrict__ Bl,
                                                 float* __restrict__ C, int N) {
    extern __shared__ __nv_bfloat16 smg[];

    const int tid  = threadIdx.x;
    const int lane = tid & 31;
    const int warp = tid >> 5;
    const int wm = (warp & 1) * 64;
    const int wn = (warp >> 1) * 32;
    const int g  = lane >> 2;
    const int tg = lane & 3;

    const int bm = blockIdx.y * 128;
    const int bn = blockIdx.x * 128;

    const __nv_bfloat16* gsrc[4];
    gsrc[0] = Ah + (size_t)bm * KDIM;
    gsrc[1] = Al + (size_t)bm * KDIM;
    gsrc[2] = Bh + (size_t)bn * KDIM;
    gsrc[3] = Bl + (size_t)bn * KDIM;

    const int row_st = tid >> 2;
    const int c8_st  = (tid & 3) * 8;

    float acc[4][4][4];
#pragma unroll
    for (int mt = 0; mt < 4; mt++)
#pragma unroll
        for (int nt = 0; nt < 4; nt++)
#pragma unroll
            for (int e = 0; e < 4; e++) acc[mt][nt][e] = 0.f;

    const int NCH = KDIM / GBK2;

#pragma unroll
    for (int t = 0; t < 4; t++) {
        __nv_bfloat16* st = smg + t * GTILE;
#pragma unroll
        for (int j = 0; j < 2; j++) {
            int row = row_st + j * 64;
            cp16(st + row * SSTR + c8_st, gsrc[t] + (size_t)row * KDIM + c8_st);
        }
    }
    CP_COMMIT();

    for (int k = 0; k < NCH; k++) {
        if (k + 1 < NCH) {
            const int k0n = (k + 1) * GBK2;
            __nv_bfloat16* stage = smg + ((k + 1) & 1) * GSTAGE;
#pragma unroll
            for (int t = 0; t < 4; t++) {
                __nv_bfloat16* st = stage + t * GTILE;
#pragma unroll
                for (int j = 0; j < 2; j++) {
                    int row = row_st + j * 64;
                    cp16(st + row * SSTR + c8_st,
                         gsrc[t] + (size_t)row * KDIM + k0n + c8_st);
                }
            }
            CP_COMMIT();
            CP_WAIT1();
        } else {
            CP_WAIT0();
        }
        __syncthreads();

        const __nv_bfloat16* sAh = smg + (k & 1) * GSTAGE;
        const __nv_bfloat16* sAl = sAh + GTILE;
        const __nv_bfloat16* sBh = sAl + GTILE;
        const __nv_bfloat16* sBl = sBh + GTILE;

#pragma unroll
        for (int ks = 0; ks < 2; ks++) {
            const int kk = ks * 16;
            uint32_t ah[4][4], al[4][4], bh[4][2], bl[4][2];
#pragma unroll
            for (int mt = 0; mt < 4; mt++) {
                int r = wm + mt * 16 + g;
                const __nv_bfloat16* p0 = sAh + r * SSTR + kk + tg * 2;
                const __nv_bfloat16* p1 = sAh + (r + 8) * SSTR + kk + tg * 2;
                ah[mt][0] = *(const uint32_t*)(p0);
                ah[mt][1] = *(const uint32_t*)(p1);
                ah[mt][2] = *(const uint32_t*)(p0 + 8);
                ah[mt][3] = *(const uint32_t*)(p1 + 8);
                const __nv_bfloat16* q0 = sAl + r * SSTR + kk + tg * 2;
                const __nv_bfloat16* q1 = sAl + (r + 8) * SSTR + kk + tg * 2;
                al[mt][0] = *(const uint32_t*)(q0);
                al[mt][1] = *(const uint32_t*)(q1);
                al[mt][2] = *(const uint32_t*)(q0 + 8);
                al[mt][3] = *(const uint32_t*)(q1 + 8);
            }
#pragma unroll
            for (int nt = 0; nt < 4; nt++) {
                int rb = wn + nt * 8 + g;
                const __nv_bfloat16* p = sBh + rb * SSTR + kk + tg * 2;
                bh[nt][0] = *(const uint32_t*)(p);
                bh[nt][1] = *(const uint32_t*)(p + 8);
                const __nv_bfloat16* q = sBl + rb * SSTR + kk + tg * 2;
                bl[nt][0] = *(const uint32_t*)(q);
                bl[nt][1] = *(const uint32_t*)(q + 8);
            }
#pragma unroll
            for (int mt = 0; mt < 4; mt++)
#pragma unroll
                for (int nt = 0; nt < 4; nt++) {
                    mma16816(acc[mt][nt], ah[mt], bh[nt]);
                    mma16816(acc[mt][nt], ah[mt], bl[nt]);
                    mma16816(acc[mt][nt], al[mt], bh[nt]);
                }
        }
        __syncthreads();
    }

#pragma unroll
    for (int mt = 0; mt < 4; mt++) {
#pragma unroll
        for (int nt = 0; nt < 4; nt++) {
            int row = bm + wm + mt * 16 + g;
            int col = bn + wn + nt * 8 + tg * 2;
            *(float2*)(C + (size_t)row * N + col) =
                make_float2(acc[mt][nt][0], acc[mt][nt][1]);
            *(float2*)(C + (size_t)(row + 8) * N + col) =
                make_float2(acc[mt][nt][2], acc[mt][nt][3]);
        }
    }
}

// ---------------- norm scalars + V hi/lo split -------------------------------
// reference: q = rsqrt(mean(q*q)+eps) * q_weight  (q itself dropped) -> only
// the scalar r survives; weights are folded into the analytic G table.
__global__ void rnorm_kernel(const float* __restrict__ qkv,
                             float* __restrict__ rq, float* __restrict__ rk,
                             __nv_bfloat16* __restrict__ Vh,
                             __nv_bfloat16* __restrict__ Vl) {
    const int m = blockIdx.x;
    const int hy = blockIdx.y;
    const int b = m / TT, t = m % TT;
    const int d = threadIdx.x;

    float x = qkv[(size_t)m * QKV_OUT + (size_t)hy * DD + d];

    if (hy < HH + KVH) {
        __shared__ float red[4];
        float ss = x * x;
#pragma unroll
        for (int o = 16; o; o >>= 1) ss += __shfl_xor_sync(0xffffffffu, ss, o);
        if ((d & 31) == 0) red[d >> 5] = ss;
        __syncthreads();
        if (d == 0) {
            float tot = red[0] + red[1] + red[2] + red[3];
            float r = rsqrtf(tot * (1.0f / DD) + 1e-6f);
            if (hy < HH) rq[((size_t)b * HH + hy) * TT + t] = r * SCALE_F;
            else         rk[((size_t)b * KVH + (hy - HH)) * TT + t] = r;
        }
    } else {
        int vh = hy - HH - KVH;
        __nv_bfloat16 hv = __float2bfloat16(x);
        size_t idx = (((size_t)b * KVH + vh) * TT + t) * DD + d;
        Vh[idx] = hv;
        Vl[idx] = __float2bfloat16(x - __bfloat162float(hv));
    }
}

// ---------------- analytic rope-kernel table ---------------------------------
// G_h(delta) = sum_i A_i cos(delta*invf_i) + B_i sin(delta*invf_i)
// A_i = qw[i]kw[i] + qw[i+64]kw[i+64], B_i = qw[i]kw[i+64] - qw[i+64]kw[i]
__global__ void build_G(const float* __restrict__ qw,
                        const float* __restrict__ kw,
                        float* __restrict__ G) {
    const int h = blockIdx.y;
    const int kv = h / GROUP;
    const int tx = threadIdx.x;
    __shared__ float sw[256];
    __shared__ double sinv[64];
    sw[tx] = qw[h * DD + tx];
    sw[128 + tx] = kw[kv * DD + tx];
    if (tx < 64) sinv[tx] = exp(-(double)tx / 64.0 * log(10000.0));
    __syncthreads();
    int dix = blockIdx.x * 128 + tx;
    if (dix >= 4095) return;
    double delta = (double)(dix - 2047);
    const double tp = 6.283185307179586476925286766559;
    float acc = 0.f;
    for (int i = 0; i < 64; i++) {
        double th = delta * sinv[i];
        th -= floor(th * (1.0 / tp)) * tp;
        float sf, cf;
        sincosf((float)th, &sf, &cf);
        float a = sw[i], bq = sw[i + 64], ap = sw[128 + i], bp = sw[192 + i];
        acc += (a * ap + bq * bp) * cf + (a * bp - bq * ap) * sf;
    }
    G[(size_t)h * 4096 + dix] = acc;
}

// ---------------- Flash attention (analytic S + HMMA PV) ---------------------
#define BQA 128
#define BKA 64
#define KSTR 136
#define ATILE (BKA * KSTR)               // bf16 elems per tile
#define ASTAGE (2 * ATILE)               // Vh, Vl
#define AG_OFF (2 * ASTAGE)              // bf16-elem offset of G/rk region
// bytes: 2 stages of (Vh,Vl) + 2x192 G floats + 2x64 rk floats
#define ATT_SMEM (2 * ASTAGE * 2 + 2 * 192 * 4 + 2 * 64 * 4)

__global__ __launch_bounds__(256) void attn_hmma(
    const float* __restrict__ rq_, const float* __restrict__ rk_,
    const float* __restrict__ G_,
    const __nv_bfloat16* __restrict__ Vh_, const __nv_bfloat16* __restrict__ Vl_,
    __nv_bfloat16* __restrict__ Ohi, __nv_bfloat16* __restrict__ Olo) {
    extern __shared__ __nv_bfloat16 smn[];
    float* sG  = (float*)(smn + AG_OFF);         // [2][192]
    float* sRk = sG + 2 * 192;                   // [2][64]

    const int tid  = threadIdx.x;
    const int lane = tid & 31;
    const int warp = tid >> 5;
    const int g  = lane >> 2;
    const int tg = lane & 3;

    const int qt = blockIdx.x, h = blockIdx.y, b = blockIdx.z;
    const int kvh = h / GROUP;
    const int row0 = warp * 16;

    const __nv_bfloat16* vh_base = Vh_ + ((size_t)b * KVH + kvh) * TT * DD;
    const __nv_bfloat16* vl_base = Vl_ + ((size_t)b * KVH + kvh) * TT * DD;
    const float* rk_base = rk_ + ((size_t)b * KVH + kvh) * TT;
    const float* G_base  = G_ + (size_t)h * 4096;

    // per-thread row norm scalars (SCALE folded in)
    const float* rq_base = rq_ + ((size_t)b * HH + h) * TT + (size_t)qt * BQA;
    const float rq0 = rq_base[row0 + g];
    const float rq1 = rq_base[row0 + g + 8];

    const int row_st = tid >> 4;          // 0..15
    const int c8_st  = (tid & 15) << 3;   // 0..120

    float oacc[16][4];
#pragma unroll
    for (int nt = 0; nt < 16; nt++)
#pragma unroll
        for (int e = 0; e < 4; e++) oacc[nt][e] = 0.f;
    float m0 = -1e30f, m1 = -1e30f, l0 = 0.f, l1 = 0.f;

    const int NKT = TT / BKA;
    // G segment base (float index into G_base) for chunk kt:
    //   idxbase(kt) = qt*128 - kt*64 + 1984   (16B aligned, 192 floats)
    // smem index of S element = rowlocal - col + 63

    // prefetch chunk 0 -> stage 0
    {
#pragma unroll
        for (int j = 0; j < 4; j++) {
            int row = row_st + j * 16;
            cp16(smn + row * KSTR + c8_st, vh_base + (size_t)row * DD + c8_st);
            cp16(smn + ATILE + row * KSTR + c8_st, vl_base + (size_t)row * DD + c8_st);
        }
        if (tid < 48) cp16(sG + tid * 4, G_base + (qt * 128 + 1984) + tid * 4);
        else if (tid < 64) cp16(sRk + (tid - 48) * 4, rk_base + (tid - 48) * 4);
    }
    CP_COMMIT();

    for (int kt = 0; kt < NKT; kt++) {
        if (kt + 1 < NKT) {
            __nv_bfloat16* stage = smn + ((kt + 1) & 1) * ASTAGE;
            const size_t goff = (size_t)(kt + 1) * BKA * DD;
#pragma unroll
            for (int j = 0; j < 4; j++) {
                int row = row_st + j * 16;
                cp16(stage + row * KSTR + c8_st, vh_base + goff + (size_t)row * DD + c8_st);
                cp16(stage + ATILE + row * KSTR + c8_st,
                     vl_base + goff + (size_t)row * DD + c8_st);
            }
            int st = (kt + 1) & 1;
            if (tid < 48)
                cp16(sG + st * 192 + tid * 4,
                     G_base + (qt * 128 - (kt + 1) * 64 + 1984) + tid * 4);
            else if (tid < 64)
                cp16(sRk + st * 64 + (tid - 48) * 4,
                     rk_base + (kt + 1) * 64 + (tid - 48) * 4);
            CP_COMMIT();
            CP_WAIT1();
        } else {
            CP_WAIT0();
        }
        __syncthreads();

        const int st = kt & 1;
        const uint32_t uVh = smem_u32(smn + st * ASTAGE);
        const uint32_t uVl = uVh + ATILE * 2;
        const float* gseg = sG + st * 192;
        const float* rks  = sRk + st * 64;

        // ---- S = rq * rk * G(delta)  (analytic, no MMA) ----
        float s[8][4];
        const int ib0 = row0 + g + 63;
#pragma unroll
        for (int nt = 0; nt < 8; nt++) {
            int col0 = nt * 8 + 2 * tg;
            float rk0 = rks[col0], rk1 = rks[col0 + 1];
            float g00 = gseg[ib0 - col0], g01 = gseg[ib0 - col0 - 1];
            float g10 = gseg[ib0 + 8 - col0], g11 = gseg[ib0 + 7 - col0];
            s[nt][0] = rq0 * rk0 * g00;
            s[nt][1] = rq0 * rk1 * g01;
            s[nt][2] = rq1 * rk0 * g10;
            s[nt][3] = rq1 * rk1 * g11;
        }

        // ---- online softmax ----
        float cm0 = -1e30f, cm1 = -1e30f;
#pragma unroll
        for (int nt = 0; nt < 8; nt++) {
            cm0 = fmaxf(cm0, fmaxf(s[nt][0], s[nt][1]));
            cm1 = fmaxf(cm1, fmaxf(s[nt][2], s[nt][3]));
        }
        cm0 = fmaxf(cm0, __shfl_xor_sync(0xffffffffu, cm0, 1));
        cm0 = fmaxf(cm0, __shfl_xor_sync(0xffffffffu, cm0, 2));
        cm1 = fmaxf(cm1, __shfl_xor_sync(0xffffffffu, cm1, 1));
        cm1 = fmaxf(cm1, __shfl_xor_sync(0xffffffffu, cm1, 2));
        float mn0 = fmaxf(m0, cm0), mn1 = fmaxf(m1, cm1);
        float alpha0 = __expf(m0 - mn0), alpha1 = __expf(m1 - mn1);
        float ls0 = 0.f, ls1 = 0.f;
#pragma unroll
        for (int nt = 0; nt < 8; nt++) {
            s[nt][0] = __expf(s[nt][0] - mn0);
            s[nt][1] = __expf(s[nt][1] - mn0);
            s[nt][2] = __expf(s[nt][2] - mn1);
            s[nt][3] = __expf(s[nt][3] - mn1);
            ls0 += s[nt][0] + s[nt][1];
            ls1 += s[nt][2] + s[nt][3];
        }
        ls0 += __shfl_xor_sync(0xffffffffu, ls0, 1);
        ls0 += __shfl_xor_sync(0xffffffffu, ls0, 2);
        ls1 += __shfl_xor_sync(0xffffffffu, ls1, 1);
        ls1 += __shfl_xor_sync(0xffffffffu, ls1, 2);
        l0 = l0 * alpha0 + ls0;
        l1 = l1 * alpha1 + ls1;
        m0 = mn0; m1 = mn1;
#pragma unroll
        for (int nt = 0; nt < 16; nt++) {
            oacc[nt][0] *= alpha0; oacc[nt][1] *= alpha0;
            oacc[nt][2] *= alpha1; oacc[nt][3] *= alpha1;
        }

        // ---- P -> bf16 hi/lo A-fragments ----
        uint32_t pah[4][4], pal[4][4];
#pragma unroll
        for (int s4 = 0; s4 < 4; s4++) {
            float c0 = s[2 * s4][0],     c1 = s[2 * s4][1];
            float c2 = s[2 * s4][2],     c3 = s[2 * s4][3];
            float d0 = s[2 * s4 + 1][0], d1 = s[2 * s4 + 1][1];
            float d2 = s[2 * s4 + 1][2], d3 = s[2 * s4 + 1][3];
            float hh;
            pah[s4][0] = pack_bf2(c0, c1);
            pah[s4][1] = pack_bf2(c2, c3);
            pah[s4][2] = pack_bf2(d0, d1);
            pah[s4][3] = pack_bf2(d2, d3);
            hh = __bfloat162float(__float2bfloat16(c0)); c0 -= hh;
            hh = __bfloat162float(__float2bfloat16(c1)); c1 -= hh;
            hh = __bfloat162float(__float2bfloat16(c2)); c2 -= hh;
            hh = __bfloat162float(__float2bfloat16(c3)); c3 -= hh;
            hh = __bfloat162float(__float2bfloat16(d0)); d0 -= hh;
            hh = __bfloat162float(__float2bfloat16(d1)); d1 -= hh;
            hh = __bfloat162float(__float2bfloat16(d2)); d2 -= hh;
            hh = __bfloat162float(__float2bfloat16(d3)); d3 -= hh;
            pal[s4][0] = pack_bf2(c0, c1);
            pal[s4][1] = pack_bf2(c2, c3);
            pal[s4][2] = pack_bf2(d0, d1);
            pal[s4][3] = pack_bf2(d2, d3);
        }

        // ---- O += P V ----
#pragma unroll
        for (int p = 0; p < 8; p++) {
#pragma unroll
            for (int s4 = 0; s4 < 4; s4++) {
                int krow = s4 * 16 + (lane & 15);
                int dcol = p * 16 + ((lane >> 4) << 3);
                uint32_t bh[4], bl[4];
                ldsm_x4_t(bh[0], bh[1], bh[2], bh[3], uVh + (krow * KSTR + dcol) * 2);
                ldsm_x4_t(bl[0], bl[1], bl[2], bl[3], uVl + (krow * KSTR + dcol) * 2);
                mma16816(oacc[2 * p],     pah[s4], bh + 0);
                mma16816(oacc[2 * p],     pah[s4], bl + 0);
                mma16816(oacc[2 * p],     pal[s4], bh + 0);
                mma16816(oacc[2 * p + 1], pah[s4], bh + 2);
                mma16816(oacc[2 * p + 1], pah[s4], bl + 2);
                mma16816(oacc[2 * p + 1], pal[s4], bh + 2);
            }
        }
        __syncthreads();
    }

    // ---- epilogue: normalize, split hi/lo into Wo-GEMM A buffers ----
    float inv0 = 1.0f / l0, inv1 = 1.0f / l1;
    int t0 = qt * BQA + row0 + g;
#pragma unroll
    for (int nt = 0; nt < 16; nt++) {
        int d = nt * 8 + 2 * tg;
        float o0 = oacc[nt][0] * inv0, o1 = oacc[nt][1] * inv0;
        float o2 = oacc[nt][2] * inv1, o3 = oacc[nt][3] * inv1;
        size_t i0 = ((size_t)b * TT + t0) * KDIM + (size_t)h * DD + d;
        size_t i1 = ((size_t)b * TT + t0 + 8) * KDIM + (size_t)h * DD + d;
        float h0 = __bfloat162float(__float2bfloat16(o0));
        float h1 = __bfloat162float(__float2bfloat16(o1));
        float h2 = __bfloat162float(__float2bfloat16(o2));
        float h3 = __bfloat162float(__float2bfloat16(o3));
        *(uint32_t*)(Ohi + i0) = pack_bf2(o0, o1);
        *(uint32_t*)(Olo + i0) = pack_bf2(o0 - h0, o1 - h1);
        *(uint32_t*)(Ohi + i1) = pack_bf2(o2, o3);
        *(uint32_t*)(Olo + i1) = pack_bf2(o2 - h2, o3 - h3);
    }
}

// ---------------- launch ------------------------------------------------------
extern "C" void kernel_launch(void* const* d_in, const int* in_sizes, int n_in,
                              void* d_out, int out_size) {
    const float* hidden = (const float*)d_in[0];
    const float* Wqkv   = (const float*)d_in[1];
    const float* Wo     = (const float*)d_in[2];
    const float* qw     = (const float*)d_in[3];
    const float* kw     = (const float*)d_in[4];
    float* out = (float*)d_out;

    float *qkv, *rq, *rk, *G;
    __nv_bfloat16 *ahi, *alo, *bhi, *blo, *vh, *vl;
    cudaGetSymbolAddress((void**)&qkv, g_qkv);
    cudaGetSymbolAddress((void**)&ahi, g_ahi);
    cudaGetSymbolAddress((void**)&alo, g_alo);
    cudaGetSymbolAddress((void**)&bhi, g_bhi);
    cudaGetSymbolAddress((void**)&blo, g_blo);
    cudaGetSymbolAddress((void**)&vh,  g_vh);
    cudaGetSymbolAddress((void**)&vl,  g_vl);
    cudaGetSymbolAddress((void**)&rq,  g_rq);
    cudaGetSymbolAddress((void**)&rk,  g_rk);
    cudaGetSymbolAddress((void**)&G,   g_G);

    cudaFuncSetAttribute(attn_hmma, cudaFuncAttributeMaxDynamicSharedMemorySize,
                         ATT_SMEM);
    cudaFuncSetAttribute(hmma_gemm, cudaFuncAttributeMaxDynamicSharedMemorySize,
                         GEMM_SMEM);

    // 0) analytic rope-kernel table (independent of projections)
    {
        dim3 grid(32, HH);
        build_G<<<grid, 128>>>(qw, kw, G);
    }

    // 1) convert inputs to bf16 hi/lo
    cvt_hilo<<<1024, 256>>>(hidden, ahi, alo, (size_t)MT * KDIM);
    cvt_hilo<<<1024, 256>>>(Wqkv, bhi, blo, (size_t)QKV_OUT * KDIM);

    // 2) QKV projection
    {
        dim3 grid(QKV_OUT / 128, MT / 128);
        hmma_gemm<<<grid, 256, GEMM_SMEM>>>(ahi, alo, bhi, blo, qkv, QKV_OUT);
    }

    // 3) norm scalars + V hi/lo
    {
        dim3 grid(MT, HH + 2 * KVH);
        rnorm_kernel<<<grid, DD>>>(qkv, rq, rk, vh, vl);
    }

    // 4) Attention (analytic S + HMMA PV) -> hi/lo into Wo-GEMM A buffers
    {
        dim3 grid(TT / BQA, HH, BB);
        attn_hmma<<<grid, 256, ATT_SMEM>>>(rq, rk, G, vh, vl, ahi, alo);
    }

    // 5) Output projection
    cvt_hilo<<<1024, 256>>>(Wo, bhi, blo, (size_t)HID * KDIM);
    {
        dim3 grid(HID / 128, MT / 128);
        hmma_gemm<<<grid, 256, GEMM_SMEM>>>(ahi, alo, bhi, blo, out, HID);
    }
}

// round 16
// speedup vs baseline: 4.1208x; 1.0165x over previous
#include <cuda_runtime.h>
#include <cuda_bf16.h>
#include <math.h>
#include <stdint.h>

// Problem constants
#define BB 2
#define TT 2048
#define HID 4096
#define HH 32
#define KVH 4
#define DD 128
#define GROUP 8
#define QKV_OUT ((HH + 2*KVH)*DD)   // 5120
#define MT (BB*TT)                  // 4096
#define KDIM 4096
#define SCALE_F 0.08838834764831845f

// ---------------- scratch (device globals; no allocations allowed) ------------
__device__ float g_qkv[(size_t)MT * QKV_OUT];

__device__ __nv_bfloat16 g_ahi[(size_t)MT * KDIM];
__device__ __nv_bfloat16 g_alo[(size_t)MT * KDIM];
__device__ __nv_bfloat16 g_bhi[(size_t)QKV_OUT * KDIM];
__device__ __nv_bfloat16 g_blo[(size_t)QKV_OUT * KDIM];

__device__ __nv_bfloat16 g_vh[(size_t)BB * KVH * TT * DD];
__device__ __nv_bfloat16 g_vl[(size_t)BB * KVH * TT * DD];

__device__ float g_rq[(size_t)BB * HH * TT];    // SCALE * rsqrt(mean q^2 + eps)
__device__ float g_rk[(size_t)BB * KVH * TT];   // rsqrt(mean k^2 + eps)
__device__ float g_G[(size_t)HH * 4096];        // per-head rope kernel table

// ================= helpers ===================================================
__device__ __forceinline__ void mma16816(float* c, const uint32_t* a, const uint32_t* b) {
    asm volatile("mma.sync.aligned.m16n8k16.row.col.f32.bf16.bf16.f32 "
                 "{%0,%1,%2,%3}, {%4,%5,%6,%7}, {%8,%9}, {%0,%1,%2,%3};"
                 : "+f"(c[0]), "+f"(c[1]), "+f"(c[2]), "+f"(c[3])
                 : "r"(a[0]), "r"(a[1]), "r"(a[2]), "r"(a[3]),
                   "r"(b[0]), "r"(b[1]));
}
__device__ __forceinline__ void ldsm_x4(uint32_t& r0, uint32_t& r1, uint32_t& r2,
                                        uint32_t& r3, uint32_t addr) {
    asm volatile("ldmatrix.sync.aligned.m8n8.x4.shared.b16 {%0,%1,%2,%3}, [%4];"
                 : "=r"(r0), "=r"(r1), "=r"(r2), "=r"(r3) : "r"(addr));
}
__device__ __forceinline__ void ldsm_x4_t(uint32_t& r0, uint32_t& r1, uint32_t& r2,
                                          uint32_t& r3, uint32_t addr) {
    asm volatile("ldmatrix.sync.aligned.m8n8.x4.trans.shared.b16 {%0,%1,%2,%3}, [%4];"
                 : "=r"(r0), "=r"(r1), "=r"(r2), "=r"(r3) : "r"(addr));
}
__device__ __forceinline__ uint32_t smem_u32(const void* p) {
    uint32_t a;
    asm("{ .reg .u64 t; cvta.to.shared.u64 t, %1; cvt.u32.u64 %0, t; }"
        : "=r"(a) : "l"(p));
    return a;
}
__device__ __forceinline__ uint32_t pack_bf2(float x, float y) {
    __nv_bfloat162 h = __floats2bfloat162_rn(x, y);
    return *(uint32_t*)&h;
}
__device__ __forceinline__ void cp16(void* smem_dst, const void* gsrc) {
    uint32_t d = smem_u32(smem_dst);
    asm volatile("cp.async.cg.shared.global [%0], [%1], 16;" :: "r"(d), "l"(gsrc));
}
#define CP_COMMIT() asm volatile("cp.async.commit_group;" ::: "memory")
#define CP_WAIT1()  asm volatile("cp.async.wait_group 1;" ::: "memory")
#define CP_WAIT0()  asm volatile("cp.async.wait_group 0;" ::: "memory")

// ================= hi/lo conversion ==========================================
__global__ void cvt_hilo(const float* __restrict__ src,
                         __nv_bfloat16* __restrict__ hi,
                         __nv_bfloat16* __restrict__ lo, size_t n) {
    size_t i = (size_t)blockIdx.x * blockDim.x + threadIdx.x;
    size_t stride = (size_t)gridDim.x * blockDim.x;
    for (; i < n / 4; i += stride) {
        float4 x = ((const float4*)src)[i];
        __nv_bfloat16 h0 = __float2bfloat16(x.x);
        __nv_bfloat16 h1 = __float2bfloat16(x.y);
        __nv_bfloat16 h2 = __float2bfloat16(x.z);
        __nv_bfloat16 h3 = __float2bfloat16(x.w);
        __nv_bfloat16 l0 = __float2bfloat16(x.x - __bfloat162float(h0));
        __nv_bfloat16 l1 = __float2bfloat16(x.y - __bfloat162float(h1));
        __nv_bfloat16 l2 = __float2bfloat16(x.z - __bfloat162float(h2));
        __nv_bfloat16 l3 = __float2bfloat16(x.w - __bfloat162float(h3));
        __nv_bfloat162 hp0, hp1, lp0, lp1;
        hp0.x = h0; hp0.y = h1; hp1.x = h2; hp1.y = h3;
        lp0.x = l0; lp0.y = l1; lp1.x = l2; lp1.y = l3;
        ((__nv_bfloat162*)hi)[i * 2 + 0] = hp0;
        ((__nv_bfloat162*)hi)[i * 2 + 1] = hp1;
        ((__nv_bfloat162*)lo)[i * 2 + 0] = lp0;
        ((__nv_bfloat162*)lo)[i * 2 + 1] = lp1;
    }
}

// ================= HMMA GEMM (cp.async 2-stage + ldmatrix): C = A * B^T ======
#define GBK2 32
#define SSTR 40
#define GTILE (128 * SSTR)
#define GSTAGE (4 * GTILE)
#define GEMM_SMEM (2 * GSTAGE * 2)

__global__ __launch_bounds__(256) void hmma_gemm(const __nv_bfloat16* __restrict__ Ah,
                                                 const __nv_bfloat16* __restrict__ Al,
                                                 const __nv_bfloat16* __restrict__ Bh,
                                                 const __nv_bfloat16* __restrict__ Bl,
                                                 float* __restrict__ C, int N) {
    extern __shared__ __nv_bfloat16 smg[];

    const int tid  = threadIdx.x;
    const int lane = tid & 31;
    const int warp = tid >> 5;
    const int wm = (warp & 1) * 64;
    const int wn = (warp >> 1) * 32;
    const int g  = lane >> 2;
    const int tg = lane & 3;

    const int bm = blockIdx.y * 128;
    const int bn = blockIdx.x * 128;

    const __nv_bfloat16* gsrc[4];
    gsrc[0] = Ah + (size_t)bm * KDIM;
    gsrc[1] = Al + (size_t)bm * KDIM;
    gsrc[2] = Bh + (size_t)bn * KDIM;
    gsrc[3] = Bl + (size_t)bn * KDIM;

    const int row_st = tid >> 2;
    const int c8_st  = (tid & 3) * 8;

    // ldmatrix lane addressing (in bf16-element units, relative to tile base)
    // A (m16 x k16, x4): lanes 0-7 rows+0..7 @kk, 8-15 rows+8..15 @kk,
    //                    16-23 rows+0..7 @kk+8, 24-31 rows+8..15 @kk+8
    const int a_lrow = (lane & 7) + ((lane >> 3) & 1) * 8;
    const int a_lcol = (lane >> 4) * 8;
    // B (two n8 tiles x k16, x4): lanes 0-7 n+0..7 @kk, 8-15 n+0..7 @kk+8,
    //                             16-23 n+8..15 @kk, 24-31 n+8..15 @kk+8
    const int b_lrow = (lane & 7) + ((lane >> 4) << 3);
    const int b_lcol = ((lane >> 3) & 1) << 3;

    float acc[4][4][4];
#pragma unroll
    for (int mt = 0; mt < 4; mt++)
#pragma unroll
        for (int nt = 0; nt < 4; nt++)
#pragma unroll
            for (int e = 0; e < 4; e++) acc[mt][nt][e] = 0.f;

    const int NCH = KDIM / GBK2;

#pragma unroll
    for (int t = 0; t < 4; t++) {
        __nv_bfloat16* st = smg + t * GTILE;
#pragma unroll
        for (int j = 0; j < 2; j++) {
            int row = row_st + j * 64;
            cp16(st + row * SSTR + c8_st, gsrc[t] + (size_t)row * KDIM + c8_st);
        }
    }
    CP_COMMIT();

    for (int k = 0; k < NCH; k++) {
        if (k + 1 < NCH) {
            const int k0n = (k + 1) * GBK2;
            __nv_bfloat16* stage = smg + ((k + 1) & 1) * GSTAGE;
#pragma unroll
            for (int t = 0; t < 4; t++) {
                __nv_bfloat16* st = stage + t * GTILE;
#pragma unroll
                for (int j = 0; j < 2; j++) {
                    int row = row_st + j * 64;
                    cp16(st + row * SSTR + c8_st,
                         gsrc[t] + (size_t)row * KDIM + k0n + c8_st);
                }
            }
            CP_COMMIT();
            CP_WAIT1();
        } else {
            CP_WAIT0();
        }
        __syncthreads();

        const uint32_t uAh = smem_u32(smg + (k & 1) * GSTAGE);
        const uint32_t uAl = uAh + GTILE * 2;
        const uint32_t uBh = uAl + GTILE * 2;
        const uint32_t uBl = uBh + GTILE * 2;

#pragma unroll
        for (int ks = 0; ks < 2; ks++) {
            const int kk = ks * 16;
            uint32_t ah[4][4], al[4][4], bh[4][2], bl[4][2];
#pragma unroll
            for (int mt = 0; mt < 4; mt++) {
                uint32_t off = ((wm + mt * 16 + a_lrow) * SSTR + kk + a_lcol) * 2;
                ldsm_x4(ah[mt][0], ah[mt][1], ah[mt][2], ah[mt][3], uAh + off);
                ldsm_x4(al[mt][0], al[mt][1], al[mt][2], al[mt][3], uAl + off);
            }
#pragma unroll
            for (int p = 0; p < 2; p++) {
                uint32_t off = ((wn + p * 16 + b_lrow) * SSTR + kk + b_lcol) * 2;
                ldsm_x4(bh[2 * p][0], bh[2 * p][1], bh[2 * p + 1][0], bh[2 * p + 1][1],
                        uBh + off);
                ldsm_x4(bl[2 * p][0], bl[2 * p][1], bl[2 * p + 1][0], bl[2 * p + 1][1],
                        uBl + off);
            }
#pragma unroll
            for (int mt = 0; mt < 4; mt++)
#pragma unroll
                for (int nt = 0; nt < 4; nt++) {
                    mma16816(acc[mt][nt], ah[mt], bh[nt]);
                    mma16816(acc[mt][nt], ah[mt], bl[nt]);
                    mma16816(acc[mt][nt], al[mt], bh[nt]);
                }
        }
        __syncthreads();
    }

#pragma unroll
    for (int mt = 0; mt < 4; mt++) {
#pragma unroll
        for (int nt = 0; nt < 4; nt++) {
            int row = bm + wm + mt * 16 + g;
            int col = bn + wn + nt * 8 + tg * 2;
            *(float2*)(C + (size_t)row * N + col) =
                make_float2(acc[mt][nt][0], acc[mt][nt][1]);
            *(float2*)(C + (size_t)(row + 8) * N + col) =
                make_float2(acc[mt][nt][2], acc[mt][nt][3]);
        }
    }
}

// ---------------- norm scalars + V hi/lo split -------------------------------
__global__ void rnorm_kernel(const float* __restrict__ qkv,
                             float* __restrict__ rq, float* __restrict__ rk,
                             __nv_bfloat16* __restrict__ Vh,
                             __nv_bfloat16* __restrict__ Vl) {
    const int m = blockIdx.x;
    const int hy = blockIdx.y;
    const int b = m / TT, t = m % TT;
    const int d = threadIdx.x;

    float x = qkv[(size_t)m * QKV_OUT + (size_t)hy * DD + d];

    if (hy < HH + KVH) {
        __shared__ float red[4];
        float ss = x * x;
#pragma unroll
        for (int o = 16; o; o >>= 1) ss += __shfl_xor_sync(0xffffffffu, ss, o);
        if ((d & 31) == 0) red[d >> 5] = ss;
        __syncthreads();
        if (d == 0) {
            float tot = red[0] + red[1] + red[2] + red[3];
            float r = rsqrtf(tot * (1.0f / DD) + 1e-6f);
            if (hy < HH) rq[((size_t)b * HH + hy) * TT + t] = r * SCALE_F;
            else         rk[((size_t)b * KVH + (hy - HH)) * TT + t] = r;
        }
    } else {
        int vh = hy - HH - KVH;
        __nv_bfloat16 hv = __float2bfloat16(x);
        size_t idx = (((size_t)b * KVH + vh) * TT + t) * DD + d;
        Vh[idx] = hv;
        Vl[idx] = __float2bfloat16(x - __bfloat162float(hv));
    }
}

// ---------------- analytic rope-kernel table ---------------------------------
__global__ void build_G(const float* __restrict__ qw,
                        const float* __restrict__ kw,
                        float* __restrict__ G) {
    const int h = blockIdx.y;
    const int kv = h / GROUP;
    const int tx = threadIdx.x;
    __shared__ float sw[256];
    __shared__ double sinv[64];
    sw[tx] = qw[h * DD + tx];
    sw[128 + tx] = kw[kv * DD + tx];
    if (tx < 64) sinv[tx] = exp(-(double)tx / 64.0 * log(10000.0));
    __syncthreads();
    int dix = blockIdx.x * 128 + tx;
    if (dix >= 4095) return;
    double delta = (double)(dix - 2047);
    const double tp = 6.283185307179586476925286766559;
    float acc = 0.f;
    for (int i = 0; i < 64; i++) {
        double th = delta * sinv[i];
        th -= floor(th * (1.0 / tp)) * tp;
        float sf, cf;
        sincosf((float)th, &sf, &cf);
        float a = sw[i], bq = sw[i + 64], ap = sw[128 + i], bp = sw[192 + i];
        acc += (a * ap + bq * bp) * cf + (a * bp - bq * ap) * sf;
    }
    G[(size_t)h * 4096 + dix] = acc;
}

// ---------------- Flash attention (analytic S + HMMA PV) ---------------------
#define BQA 128
#define BKA 64
#define KSTR 136
#define ATILE (BKA * KSTR)
#define ASTAGE (2 * ATILE)
#define AG_OFF (2 * ASTAGE)
#define ATT_SMEM (2 * ASTAGE * 2 + 2 * 192 * 4 + 2 * 64 * 4)

__global__ __launch_bounds__(256) void attn_hmma(
    const float* __restrict__ rq_, const float* __restrict__ rk_,
    const float* __restrict__ G_,
    const __nv_bfloat16* __restrict__ Vh_, const __nv_bfloat16* __restrict__ Vl_,
    __nv_bfloat16* __restrict__ Ohi, __nv_bfloat16* __restrict__ Olo) {
    extern __shared__ __nv_bfloat16 smn[];
    float* sG  = (float*)(smn + AG_OFF);
    float* sRk = sG + 2 * 192;

    const int tid  = threadIdx.x;
    const int lane = tid & 31;
    const int warp = tid >> 5;
    const int g  = lane >> 2;
    const int tg = lane & 3;

    const int qt = blockIdx.x, h = blockIdx.y, b = blockIdx.z;
    const int kvh = h / GROUP;
    const int row0 = warp * 16;

    const __nv_bfloat16* vh_base = Vh_ + ((size_t)b * KVH + kvh) * TT * DD;
    const __nv_bfloat16* vl_base = Vl_ + ((size_t)b * KVH + kvh) * TT * DD;
    const float* rk_base = rk_ + ((size_t)b * KVH + kvh) * TT;
    const float* G_base  = G_ + (size_t)h * 4096;

    const float* rq_base = rq_ + ((size_t)b * HH + h) * TT + (size_t)qt * BQA;
    const float rq0 = rq_base[row0 + g];
    const float rq1 = rq_base[row0 + g + 8];

    const int row_st = tid >> 4;
    const int c8_st  = (tid & 15) << 3;

    float oacc[16][4];
#pragma unroll
    for (int nt = 0; nt < 16; nt++)
#pragma unroll
        for (int e = 0; e < 4; e++) oacc[nt][e] = 0.f;
    float m0 = -1e30f, m1 = -1e30f, l0 = 0.f, l1 = 0.f;

    const int NKT = TT / BKA;

    {
#pragma unroll
        for (int j = 0; j < 4; j++) {
            int row = row_st + j * 16;
            cp16(smn + row * KSTR + c8_st, vh_base + (size_t)row * DD + c8_st);
            cp16(smn + ATILE + row * KSTR + c8_st, vl_base + (size_t)row * DD + c8_st);
        }
        if (tid < 48) cp16(sG + tid * 4, G_base + (qt * 128 + 1984) + tid * 4);
        else if (tid < 64) cp16(sRk + (tid - 48) * 4, rk_base + (tid - 48) * 4);
    }
    CP_COMMIT();

    for (int kt = 0; kt < NKT; kt++) {
        if (kt + 1 < NKT) {
            __nv_bfloat16* stage = smn + ((kt + 1) & 1) * ASTAGE;
            const size_t goff = (size_t)(kt + 1) * BKA * DD;
#pragma unroll
            for (int j = 0; j < 4; j++) {
                int row = row_st + j * 16;
                cp16(stage + row * KSTR + c8_st, vh_base + goff + (size_t)row * DD + c8_st);
                cp16(stage + ATILE + row * KSTR + c8_st,
                     vl_base + goff + (size_t)row * DD + c8_st);
            }
            int st = (kt + 1) & 1;
            if (tid < 48)
                cp16(sG + st * 192 + tid * 4,
                     G_base + (qt * 128 - (kt + 1) * 64 + 1984) + tid * 4);
            else if (tid < 64)
                cp16(sRk + st * 64 + (tid - 48) * 4,
                     rk_base + (kt + 1) * 64 + (tid - 48) * 4);
            CP_COMMIT();
            CP_WAIT1();
        } else {
            CP_WAIT0();
        }
        __syncthreads();

        const int st = kt & 1;
        const uint32_t uVh = smem_u32(smn + st * ASTAGE);
        const uint32_t uVl = uVh + ATILE * 2;
        const float* gseg = sG + st * 192;
        const float* rks  = sRk + st * 64;

        float s[8][4];
        const int ib0 = row0 + g + 63;
#pragma unroll
        for (int nt = 0; nt < 8; nt++) {
            int col0 = nt * 8 + 2 * tg;
            float rk0 = rks[col0], rk1 = rks[col0 + 1];
            float g00 = gseg[ib0 - col0], g01 = gseg[ib0 - col0 - 1];
            float g10 = gseg[ib0 + 8 - col0], g11 = gseg[ib0 + 7 - col0];
            s[nt][0] = rq0 * rk0 * g00;
            s[nt][1] = rq0 * rk1 * g01;
            s[nt][2] = rq1 * rk0 * g10;
            s[nt][3] = rq1 * rk1 * g11;
        }

        float cm0 = -1e30f, cm1 = -1e30f;
#pragma unroll
        for (int nt = 0; nt < 8; nt++) {
            cm0 = fmaxf(cm0, fmaxf(s[nt][0], s[nt][1]));
            cm1 = fmaxf(cm1, fmaxf(s[nt][2], s[nt][3]));
        }
        cm0 = fmaxf(cm0, __shfl_xor_sync(0xffffffffu, cm0, 1));
        cm0 = fmaxf(cm0, __shfl_xor_sync(0xffffffffu, cm0, 2));
        cm1 = fmaxf(cm1, __shfl_xor_sync(0xffffffffu, cm1, 1));
        cm1 = fmaxf(cm1, __shfl_xor_sync(0xffffffffu, cm1, 2));
        float mn0 = fmaxf(m0, cm0), mn1 = fmaxf(m1, cm1);
        float alpha0 = __expf(m0 - mn0), alpha1 = __expf(m1 - mn1);
        float ls0 = 0.f, ls1 = 0.f;
#pragma unroll
        for (int nt = 0; nt < 8; nt++) {
            s[nt][0] = __expf(s[nt][0] - mn0);
            s[nt][1] = __expf(s[nt][1] - mn0);
            s[nt][2] = __expf(s[nt][2] - mn1);
            s[nt][3] = __expf(s[nt][3] - mn1);
            ls0 += s[nt][0] + s[nt][1];
            ls1 += s[nt][2] + s[nt][3];
        }
        ls0 += __shfl_xor_sync(0xffffffffu, ls0, 1);
        ls0 += __shfl_xor_sync(0xffffffffu, ls0, 2);
        ls1 += __shfl_xor_sync(0xffffffffu, ls1, 1);
        ls1 += __shfl_xor_sync(0xffffffffu, ls1, 2);
        l0 = l0 * alpha0 + ls0;
        l1 = l1 * alpha1 + ls1;
        m0 = mn0; m1 = mn1;
#pragma unroll
        for (int nt = 0; nt < 16; nt++) {
            oacc[nt][0] *= alpha0; oacc[nt][1] *= alpha0;
            oacc[nt][2] *= alpha1; oacc[nt][3] *= alpha1;
        }

        uint32_t pah[4][4], pal[4][4];
#pragma unroll
        for (int s4 = 0; s4 < 4; s4++) {
            float c0 = s[2 * s4][0],     c1 = s[2 * s4][1];
            float c2 = s[2 * s4][2],     c3 = s[2 * s4][3];
            float d0 = s[2 * s4 + 1][0], d1 = s[2 * s4 + 1][1];
            float d2 = s[2 * s4 + 1][2], d3 = s[2 * s4 + 1][3];
            float hh;
            pah[s4][0] = pack_bf2(c0, c1);
            pah[s4][1] = pack_bf2(c2, c3);
            pah[s4][2] = pack_bf2(d0, d1);
            pah[s4][3] = pack_bf2(d2, d3);
            hh = __bfloat162float(__float2bfloat16(c0)); c0 -= hh;
            hh = __bfloat162float(__float2bfloat16(c1)); c1 -= hh;
            hh = __bfloat162float(__float2bfloat16(c2)); c2 -= hh;
            hh = __bfloat162float(__float2bfloat16(c3)); c3 -= hh;
            hh = __bfloat162float(__float2bfloat16(d0)); d0 -= hh;
            hh = __bfloat162float(__float2bfloat16(d1)); d1 -= hh;
            hh = __bfloat162float(__float2bfloat16(d2)); d2 -= hh;
            hh = __bfloat162float(__float2bfloat16(d3)); d3 -= hh;
            pal[s4][0] = pack_bf2(c0, c1);
            pal[s4][1] = pack_bf2(c2, c3);
            pal[s4][2] = pack_bf2(d0, d1);
            pal[s4][3] = pack_bf2(d2, d3);
        }

#pragma unroll
        for (int p = 0; p < 8; p++) {
#pragma unroll
            for (int s4 = 0; s4 < 4; s4++) {
                int krow = s4 * 16 + (lane & 15);
                int dcol = p * 16 + ((lane >> 4) << 3);
                uint32_t bh[4], bl[4];
                ldsm_x4_t(bh[0], bh[1], bh[2], bh[3], uVh + (krow * KSTR + dcol) * 2);
                ldsm_x4_t(bl[0], bl[1], bl[2], bl[3], uVl + (krow * KSTR + dcol) * 2);
                mma16816(oacc[2 * p],     pah[s4], bh + 0);
                mma16816(oacc[2 * p],     pah[s4], bl + 0);
                mma16816(oacc[2 * p],     pal[s4], bh + 0);
                mma16816(oacc[2 * p + 1], pah[s4], bh + 2);
                mma16816(oacc[2 * p + 1], pah[s4], bl + 2);
                mma16816(oacc[2 * p + 1], pal[s4], bh + 2);
            }
        }
        __syncthreads();
    }

    float inv0 = 1.0f / l0, inv1 = 1.0f / l1;
    int t0 = qt * BQA + row0 + g;
#pragma unroll
    for (int nt = 0; nt < 16; nt++) {
        int d = nt * 8 + 2 * tg;
        float o0 = oacc[nt][0] * inv0, o1 = oacc[nt][1] * inv0;
        float o2 = oacc[nt][2] * inv1, o3 = oacc[nt][3] * inv1;
        size_t i0 = ((size_t)b * TT + t0) * KDIM + (size_t)h * DD + d;
        size_t i1 = ((size_t)b * TT + t0 + 8) * KDIM + (size_t)h * DD + d;
        float h0 = __bfloat162float(__float2bfloat16(o0));
        float h1 = __bfloat162float(__float2bfloat16(o1));
        float h2 = __bfloat162float(__float2bfloat16(o2));
        float h3 = __bfloat162float(__float2bfloat16(o3));
        *(uint32_t*)(Ohi + i0) = pack_bf2(o0, o1);
        *(uint32_t*)(Olo + i0) = pack_bf2(o0 - h0, o1 - h1);
        *(uint32_t*)(Ohi + i1) = pack_bf2(o2, o3);
        *(uint32_t*)(Olo + i1) = pack_bf2(o2 - h2, o3 - h3);
    }
}

// ---------------- launch ------------------------------------------------------
extern "C" void kernel_launch(void* const* d_in, const int* in_sizes, int n_in,
                              void* d_out, int out_size) {
    const float* hidden = (const float*)d_in[0];
    const float* Wqkv   = (const float*)d_in[1];
    const float* Wo     = (const float*)d_in[2];
    const float* qw     = (const float*)d_in[3];
    const float* kw     = (const float*)d_in[4];
    float* out = (float*)d_out;

    float *qkv, *rq, *rk, *G;
    __nv_bfloat16 *ahi, *alo, *bhi, *blo, *vh, *vl;
    cudaGetSymbolAddress((void**)&qkv, g_qkv);
    cudaGetSymbolAddress((void**)&ahi, g_ahi);
    cudaGetSymbolAddress((void**)&alo, g_alo);
    cudaGetSymbolAddress((void**)&bhi, g_bhi);
    cudaGetSymbolAddress((void**)&blo, g_blo);
    cudaGetSymbolAddress((void**)&vh,  g_vh);
    cudaGetSymbolAddress((void**)&vl,  g_vl);
    cudaGetSymbolAddress((void**)&rq,  g_rq);
    cudaGetSymbolAddress((void**)&rk,  g_rk);
    cudaGetSymbolAddress((void**)&G,   g_G);

    cudaFuncSetAttribute(attn_hmma, cudaFuncAttributeMaxDynamicSharedMemorySize,
                         ATT_SMEM);
    cudaFuncSetAttribute(hmma_gemm, cudaFuncAttributeMaxDynamicSharedMemorySize,
                         GEMM_SMEM);

    // 0) analytic rope-kernel table
    {
        dim3 grid(32, HH);
        build_G<<<grid, 128>>>(qw, kw, G);
    }

    // 1) convert inputs to bf16 hi/lo
    cvt_hilo<<<1024, 256>>>(hidden, ahi, alo, (size_t)MT * KDIM);
    cvt_hilo<<<1024, 256>>>(Wqkv, bhi, blo, (size_t)QKV_OUT * KDIM);

    // 2) QKV projection
    {
        dim3 grid(QKV_OUT / 128, MT / 128);
        hmma_gemm<<<grid, 256, GEMM_SMEM>>>(ahi, alo, bhi, blo, qkv, QKV_OUT);
    }

    // 3) norm scalars + V hi/lo
    {
        dim3 grid(MT, HH + 2 * KVH);
        rnorm_kernel<<<grid, DD>>>(qkv, rq, rk, vh, vl);
    }

    // 4) Attention (analytic S + HMMA PV)
    {
        dim3 grid(TT / BQA, HH, BB);
        attn_hmma<<<grid, 256, ATT_SMEM>>>(rq, rk, G, vh, vl, ahi, alo);
    }

    // 5) Output projection
    cvt_hilo<<<1024, 256>>>(Wo, bhi, blo, (size_t)HID * KDIM);
    {
        dim3 grid(HID / 128, MT / 128);
        hmma_gemm<<<grid, 256, GEMM_SMEM>>>(ahi, alo, bhi, blo, out, HID);
    }
}

// round 17
// speedup vs baseline: 5.5418x; 1.3448x over previous
#include <cuda_runtime.h>
#include <cuda_fp16.h>
#include <cuda_bf16.h>
#include <math.h>
#include <stdint.h>

// Problem constants
#define BB 2
#define TT 2048
#define HID 4096
#define HH 32
#define KVH 4
#define DD 128
#define GROUP 8
#define QKV_OUT ((HH + 2*KVH)*DD)   // 5120
#define MT (BB*TT)                  // 4096
#define KDIM 4096
#define SCALE_F 0.08838834764831845f

// ---------------- scratch (device globals; no allocations allowed) ------------
__device__ float g_qkv[(size_t)MT * QKV_OUT];

__device__ __half g_ahi[(size_t)MT * KDIM];      // A hi (hidden / attn-out)
__device__ __half g_alo[(size_t)MT * KDIM];      // A lo
__device__ __half g_b16[(size_t)QKV_OUT * KDIM]; // B single fp16 (weights)

__device__ __half g_vh[(size_t)BB * KVH * TT * DD];
__device__ __half g_vl[(size_t)BB * KVH * TT * DD];

__device__ float g_rq[(size_t)BB * HH * TT];    // SCALE * rsqrt(mean q^2 + eps)
__device__ float g_rk[(size_t)BB * KVH * TT];   // rsqrt(mean k^2 + eps)
__device__ float g_G[(size_t)HH * 4096];        // per-head rope kernel table

// ================= helpers ===================================================
__device__ __forceinline__ void mma16816h(float* c, const uint32_t* a, const uint32_t* b) {
    asm volatile("mma.sync.aligned.m16n8k16.row.col.f32.f16.f16.f32 "
                 "{%0,%1,%2,%3}, {%4,%5,%6,%7}, {%8,%9}, {%0,%1,%2,%3};"
                 : "+f"(c[0]), "+f"(c[1]), "+f"(c[2]), "+f"(c[3])
                 : "r"(a[0]), "r"(a[1]), "r"(a[2]), "r"(a[3]),
                   "r"(b[0]), "r"(b[1]));
}
__device__ __forceinline__ void ldsm_x4(uint32_t& r0, uint32_t& r1, uint32_t& r2,
                                        uint32_t& r3, uint32_t addr) {
    asm volatile("ldmatrix.sync.aligned.m8n8.x4.shared.b16 {%0,%1,%2,%3}, [%4];"
                 : "=r"(r0), "=r"(r1), "=r"(r2), "=r"(r3) : "r"(addr));
}
__device__ __forceinline__ void ldsm_x4_t(uint32_t& r0, uint32_t& r1, uint32_t& r2,
                                          uint32_t& r3, uint32_t addr) {
    asm volatile("ldmatrix.sync.aligned.m8n8.x4.trans.shared.b16 {%0,%1,%2,%3}, [%4];"
                 : "=r"(r0), "=r"(r1), "=r"(r2), "=r"(r3) : "r"(addr));
}
__device__ __forceinline__ uint32_t smem_u32(const void* p) {
    uint32_t a;
    asm("{ .reg .u64 t; cvta.to.shared.u64 t, %1; cvt.u32.u64 %0, t; }"
        : "=r"(a) : "l"(p));
    return a;
}
__device__ __forceinline__ uint32_t pack_h2(float x, float y) {
    __half2 h = __floats2half2_rn(x, y);
    return *(uint32_t*)&h;
}
__device__ __forceinline__ void cp16(void* smem_dst, const void* gsrc) {
    uint32_t d = smem_u32(smem_dst);
    asm volatile("cp.async.cg.shared.global [%0], [%1], 16;" :: "r"(d), "l"(gsrc));
}
#define CP_COMMIT() asm volatile("cp.async.commit_group;" ::: "memory")
#define CP_WAIT1()  asm volatile("cp.async.wait_group 1;" ::: "memory")
#define CP_WAIT0()  asm volatile("cp.async.wait_group 0;" ::: "memory")

// ================= conversions ===============================================
__global__ void cvt_hilo16(const float* __restrict__ src,
                           __half* __restrict__ hi,
                           __half* __restrict__ lo, size_t n) {
    size_t i = (size_t)blockIdx.x * blockDim.x + threadIdx.x;
    size_t stride = (size_t)gridDim.x * blockDim.x;
    for (; i < n / 4; i += stride) {
        float4 x = ((const float4*)src)[i];
        __half h0 = __float2half_rn(x.x);
        __half h1 = __float2half_rn(x.y);
        __half h2 = __float2half_rn(x.z);
        __half h3 = __float2half_rn(x.w);
        __half l0 = __float2half_rn(x.x - __half2float(h0));
        __half l1 = __float2half_rn(x.y - __half2float(h1));
        __half l2 = __float2half_rn(x.z - __half2float(h2));
        __half l3 = __float2half_rn(x.w - __half2float(h3));
        __half2 hp0, hp1, lp0, lp1;
        hp0.x = h0; hp0.y = h1; hp1.x = h2; hp1.y = h3;
        lp0.x = l0; lp0.y = l1; lp1.x = l2; lp1.y = l3;
        ((__half2*)hi)[i * 2 + 0] = hp0;
        ((__half2*)hi)[i * 2 + 1] = hp1;
        ((__half2*)lo)[i * 2 + 0] = lp0;
        ((__half2*)lo)[i * 2 + 1] = lp1;
    }
}
__global__ void cvt_16(const float* __restrict__ src,
                       __half* __restrict__ dst, size_t n) {
    size_t i = (size_t)blockIdx.x * blockDim.x + threadIdx.x;
    size_t stride = (size_t)gridDim.x * blockDim.x;
    for (; i < n / 4; i += stride) {
        float4 x = ((const float4*)src)[i];
        __half2 p0 = __floats2half2_rn(x.x, x.y);
        __half2 p1 = __floats2half2_rn(x.z, x.w);
        ((__half2*)dst)[i * 2 + 0] = p0;
        ((__half2*)dst)[i * 2 + 1] = p1;
    }
}

// ====== HMMA GEMM (fp16, A split hi/lo, B single; 2-pass; cp.async) ==========
#define GBK2 32
#define SSTR 40
#define GTILE (128 * SSTR)
#define GSTAGE (3 * GTILE)               // Ah, Al, B
#define GEMM_SMEM (2 * GSTAGE * 2)

__global__ __launch_bounds__(256) void hmma_gemm(const __half* __restrict__ Ah,
                                                 const __half* __restrict__ Al,
                                                 const __half* __restrict__ Bw,
                                                 float* __restrict__ C, int N) {
    extern __shared__ __half smg[];

    const int tid  = threadIdx.x;
    const int lane = tid & 31;
    const int warp = tid >> 5;
    const int wm = (warp & 1) * 64;
    const int wn = (warp >> 1) * 32;
    const int g  = lane >> 2;
    const int tg = lane & 3;

    const int bm = blockIdx.y * 128;
    const int bn = blockIdx.x * 128;

    const __half* gsrc[3];
    gsrc[0] = Ah + (size_t)bm * KDIM;
    gsrc[1] = Al + (size_t)bm * KDIM;
    gsrc[2] = Bw + (size_t)bn * KDIM;

    const int row_st = tid >> 2;
    const int c8_st  = (tid & 3) * 8;

    const int a_lrow = (lane & 7) + ((lane >> 3) & 1) * 8;
    const int a_lcol = (lane >> 4) * 8;
    const int b_lrow = (lane & 7) + ((lane >> 4) << 3);
    const int b_lcol = ((lane >> 3) & 1) << 3;

    float acc[4][4][4];
#pragma unroll
    for (int mt = 0; mt < 4; mt++)
#pragma unroll
        for (int nt = 0; nt < 4; nt++)
#pragma unroll
            for (int e = 0; e < 4; e++) acc[mt][nt][e] = 0.f;

    const int NCH = KDIM / GBK2;

#pragma unroll
    for (int t = 0; t < 3; t++) {
        __half* st = smg + t * GTILE;
#pragma unroll
        for (int j = 0; j < 2; j++) {
            int row = row_st + j * 64;
            cp16(st + row * SSTR + c8_st, gsrc[t] + (size_t)row * KDIM + c8_st);
        }
    }
    CP_COMMIT();

    for (int k = 0; k < NCH; k++) {
        if (k + 1 < NCH) {
            const int k0n = (k + 1) * GBK2;
            __half* stage = smg + ((k + 1) & 1) * GSTAGE;
#pragma unroll
            for (int t = 0; t < 3; t++) {
                __half* st = stage + t * GTILE;
#pragma unroll
                for (int j = 0; j < 2; j++) {
                    int row = row_st + j * 64;
                    cp16(st + row * SSTR + c8_st,
                         gsrc[t] + (size_t)row * KDIM + k0n + c8_st);
                }
            }
            CP_COMMIT();
            CP_WAIT1();
        } else {
            CP_WAIT0();
        }
        __syncthreads();

        const uint32_t uAh = smem_u32(smg + (k & 1) * GSTAGE);
        const uint32_t uAl = uAh + GTILE * 2;
        const uint32_t uB  = uAl + GTILE * 2;

#pragma unroll
        for (int ks = 0; ks < 2; ks++) {
            const int kk = ks * 16;
            uint32_t ah[4][4], al[4][4], bf[4][2];
#pragma unroll
            for (int mt = 0; mt < 4; mt++) {
                uint32_t off = ((wm + mt * 16 + a_lrow) * SSTR + kk + a_lcol) * 2;
                ldsm_x4(ah[mt][0], ah[mt][1], ah[mt][2], ah[mt][3], uAh + off);
                ldsm_x4(al[mt][0], al[mt][1], al[mt][2], al[mt][3], uAl + off);
            }
#pragma unroll
            for (int p = 0; p < 2; p++) {
                uint32_t off = ((wn + p * 16 + b_lrow) * SSTR + kk + b_lcol) * 2;
                ldsm_x4(bf[2 * p][0], bf[2 * p][1], bf[2 * p + 1][0], bf[2 * p + 1][1],
                        uB + off);
            }
#pragma unroll
            for (int mt = 0; mt < 4; mt++)
#pragma unroll
                for (int nt = 0; nt < 4; nt++) {
                    mma16816h(acc[mt][nt], ah[mt], bf[nt]);
                    mma16816h(acc[mt][nt], al[mt], bf[nt]);
                }
        }
        __syncthreads();
    }

#pragma unroll
    for (int mt = 0; mt < 4; mt++) {
#pragma unroll
        for (int nt = 0; nt < 4; nt++) {
            int row = bm + wm + mt * 16 + g;
            int col = bn + wn + nt * 8 + tg * 2;
            *(float2*)(C + (size_t)row * N + col) =
                make_float2(acc[mt][nt][0], acc[mt][nt][1]);
            *(float2*)(C + (size_t)(row + 8) * N + col) =
                make_float2(acc[mt][nt][2], acc[mt][nt][3]);
        }
    }
}

// ---------------- norm scalars + V fp16 hi/lo split --------------------------
__global__ void rnorm_kernel(const float* __restrict__ qkv,
                             float* __restrict__ rq, float* __restrict__ rk,
                             __half* __restrict__ Vh,
                             __half* __restrict__ Vl) {
    const int m = blockIdx.x;
    const int hy = blockIdx.y;
    const int b = m / TT, t = m % TT;
    const int d = threadIdx.x;

    float x = qkv[(size_t)m * QKV_OUT + (size_t)hy * DD + d];

    if (hy < HH + KVH) {
        __shared__ float red[4];
        float ss = x * x;
#pragma unroll
        for (int o = 16; o; o >>= 1) ss += __shfl_xor_sync(0xffffffffu, ss, o);
        if ((d & 31) == 0) red[d >> 5] = ss;
        __syncthreads();
        if (d == 0) {
            float tot = red[0] + red[1] + red[2] + red[3];
            float r = rsqrtf(tot * (1.0f / DD) + 1e-6f);
            if (hy < HH) rq[((size_t)b * HH + hy) * TT + t] = r * SCALE_F;
            else         rk[((size_t)b * KVH + (hy - HH)) * TT + t] = r;
        }
    } else {
        int vh = hy - HH - KVH;
        __half hv = __float2half_rn(x);
        size_t idx = (((size_t)b * KVH + vh) * TT + t) * DD + d;
        Vh[idx] = hv;
        Vl[idx] = __float2half_rn(x - __half2float(hv));
    }
}

// ---------------- analytic rope-kernel table ---------------------------------
__global__ void build_G(const float* __restrict__ qw,
                        const float* __restrict__ kw,
                        float* __restrict__ G) {
    const int h = blockIdx.y;
    const int kv = h / GROUP;
    const int tx = threadIdx.x;
    __shared__ float sw[256];
    __shared__ double sinv[64];
    sw[tx] = qw[h * DD + tx];
    sw[128 + tx] = kw[kv * DD + tx];
    if (tx < 64) sinv[tx] = exp(-(double)tx / 64.0 * log(10000.0));
    __syncthreads();
    int dix = blockIdx.x * 128 + tx;
    if (dix >= 4095) return;
    double delta = (double)(dix - 2047);
    const double tp = 6.283185307179586476925286766559;
    float acc = 0.f;
    for (int i = 0; i < 64; i++) {
        double th = delta * sinv[i];
        th -= floor(th * (1.0 / tp)) * tp;
        float sf, cf;
        sincosf((float)th, &sf, &cf);
        float a = sw[i], bq = sw[i + 64], ap = sw[128 + i], bp = sw[192 + i];
        acc += (a * ap + bq * bp) * cf + (a * bp - bq * ap) * sf;
    }
    G[(size_t)h * 4096 + dix] = acc;
}

// ---------------- Flash attention (analytic S + fp16 HMMA PV) ----------------
#define BQA 128
#define BKA 64
#define KSTR 136
#define ATILE (BKA * KSTR)
#define ASTAGE (2 * ATILE)               // Vh, Vl
#define AG_OFF (2 * ASTAGE)
#define ATT_SMEM (2 * ASTAGE * 2 + 2 * 192 * 4 + 2 * 64 * 4)

__global__ __launch_bounds__(256) void attn_hmma(
    const float* __restrict__ rq_, const float* __restrict__ rk_,
    const float* __restrict__ G_,
    const __half* __restrict__ Vh_, const __half* __restrict__ Vl_,
    __half* __restrict__ Ohi, __half* __restrict__ Olo) {
    extern __shared__ __half smn[];
    float* sG  = (float*)(smn + AG_OFF);
    float* sRk = sG + 2 * 192;

    const int tid  = threadIdx.x;
    const int lane = tid & 31;
    const int warp = tid >> 5;
    const int g  = lane >> 2;
    const int tg = lane & 3;

    const int qt = blockIdx.x, h = blockIdx.y, b = blockIdx.z;
    const int kvh = h / GROUP;
    const int row0 = warp * 16;

    const __half* vh_base = Vh_ + ((size_t)b * KVH + kvh) * TT * DD;
    const __half* vl_base = Vl_ + ((size_t)b * KVH + kvh) * TT * DD;
    const float* rk_base = rk_ + ((size_t)b * KVH + kvh) * TT;
    const float* G_base  = G_ + (size_t)h * 4096;

    const float* rq_base = rq_ + ((size_t)b * HH + h) * TT + (size_t)qt * BQA;
    const float rq0 = rq_base[row0 + g];
    const float rq1 = rq_base[row0 + g + 8];

    const int row_st = tid >> 4;
    const int c8_st  = (tid & 15) << 3;

    float oacc[16][4];
#pragma unroll
    for (int nt = 0; nt < 16; nt++)
#pragma unroll
        for (int e = 0; e < 4; e++) oacc[nt][e] = 0.f;
    float m0 = -1e30f, m1 = -1e30f, l0 = 0.f, l1 = 0.f;

    const int NKT = TT / BKA;

    {
#pragma unroll
        for (int j = 0; j < 4; j++) {
            int row = row_st + j * 16;
            cp16(smn + row * KSTR + c8_st, vh_base + (size_t)row * DD + c8_st);
            cp16(smn + ATILE + row * KSTR + c8_st, vl_base + (size_t)row * DD + c8_st);
        }
        if (tid < 48) cp16(sG + tid * 4, G_base + (qt * 128 + 1984) + tid * 4);
        else if (tid < 64) cp16(sRk + (tid - 48) * 4, rk_base + (tid - 48) * 4);
    }
    CP_COMMIT();

    for (int kt = 0; kt < NKT; kt++) {
        if (kt + 1 < NKT) {
            __half* stage = smn + ((kt + 1) & 1) * ASTAGE;
            const size_t goff = (size_t)(kt + 1) * BKA * DD;
#pragma unroll
            for (int j = 0; j < 4; j++) {
                int row = row_st + j * 16;
                cp16(stage + row * KSTR + c8_st, vh_base + goff + (size_t)row * DD + c8_st);
                cp16(stage + ATILE + row * KSTR + c8_st,
                     vl_base + goff + (size_t)row * DD + c8_st);
            }
            int st = (kt + 1) & 1;
            if (tid < 48)
                cp16(sG + st * 192 + tid * 4,
                     G_base + (qt * 128 - (kt + 1) * 64 + 1984) + tid * 4);
            else if (tid < 64)
                cp16(sRk + st * 64 + (tid - 48) * 4,
                     rk_base + (kt + 1) * 64 + (tid - 48) * 4);
            CP_COMMIT();
            CP_WAIT1();
        } else {
            CP_WAIT0();
        }
        __syncthreads();

        const int st = kt & 1;
        const uint32_t uVh = smem_u32(smn + st * ASTAGE);
        const uint32_t uVl = uVh + ATILE * 2;
        const float* gseg = sG + st * 192;
        const float* rks  = sRk + st * 64;

        float s[8][4];
        const int ib0 = row0 + g + 63;
#pragma unroll
        for (int nt = 0; nt < 8; nt++) {
            int col0 = nt * 8 + 2 * tg;
            float rk0 = rks[col0], rk1 = rks[col0 + 1];
            float g00 = gseg[ib0 - col0], g01 = gseg[ib0 - col0 - 1];
            float g10 = gseg[ib0 + 8 - col0], g11 = gseg[ib0 + 7 - col0];
            s[nt][0] = rq0 * rk0 * g00;
            s[nt][1] = rq0 * rk1 * g01;
            s[nt][2] = rq1 * rk0 * g10;
            s[nt][3] = rq1 * rk1 * g11;
        }

        float cm0 = -1e30f, cm1 = -1e30f;
#pragma unroll
        for (int nt = 0; nt < 8; nt++) {
            cm0 = fmaxf(cm0, fmaxf(s[nt][0], s[nt][1]));
            cm1 = fmaxf(cm1, fmaxf(s[nt][2], s[nt][3]));
        }
        cm0 = fmaxf(cm0, __shfl_xor_sync(0xffffffffu, cm0, 1));
        cm0 = fmaxf(cm0, __shfl_xor_sync(0xffffffffu, cm0, 2));
        cm1 = fmaxf(cm1, __shfl_xor_sync(0xffffffffu, cm1, 1));
        cm1 = fmaxf(cm1, __shfl_xor_sync(0xffffffffu, cm1, 2));
        float mn0 = fmaxf(m0, cm0), mn1 = fmaxf(m1, cm1);
        float alpha0 = __expf(m0 - mn0), alpha1 = __expf(m1 - mn1);
        float ls0 = 0.f, ls1 = 0.f;
#pragma unroll
        for (int nt = 0; nt < 8; nt++) {
            s[nt][0] = __expf(s[nt][0] - mn0);
            s[nt][1] = __expf(s[nt][1] - mn0);
            s[nt][2] = __expf(s[nt][2] - mn1);
            s[nt][3] = __expf(s[nt][3] - mn1);
            ls0 += s[nt][0] + s[nt][1];
            ls1 += s[nt][2] + s[nt][3];
        }
        ls0 += __shfl_xor_sync(0xffffffffu, ls0, 1);
        ls0 += __shfl_xor_sync(0xffffffffu, ls0, 2);
        ls1 += __shfl_xor_sync(0xffffffffu, ls1, 1);
        ls1 += __shfl_xor_sync(0xffffffffu, ls1, 2);
        l0 = l0 * alpha0 + ls0;
        l1 = l1 * alpha1 + ls1;
        m0 = mn0; m1 = mn1;
#pragma unroll
        for (int nt = 0; nt < 16; nt++) {
            oacc[nt][0] *= alpha0; oacc[nt][1] *= alpha0;
            oacc[nt][2] *= alpha1; oacc[nt][3] *= alpha1;
        }

        // ---- P -> fp16 A-fragments (single precision pass for P) ----
        uint32_t pa[4][4];
#pragma unroll
        for (int s4 = 0; s4 < 4; s4++) {
            pa[s4][0] = pack_h2(s[2 * s4][0], s[2 * s4][1]);
            pa[s4][1] = pack_h2(s[2 * s4][2], s[2 * s4][3]);
            pa[s4][2] = pack_h2(s[2 * s4 + 1][0], s[2 * s4 + 1][1]);
            pa[s4][3] = pack_h2(s[2 * s4 + 1][2], s[2 * s4 + 1][3]);
        }

        // ---- O += P V  (V hi/lo, 2 passes) ----
#pragma unroll
        for (int p = 0; p < 8; p++) {
#pragma unroll
            for (int s4 = 0; s4 < 4; s4++) {
                int krow = s4 * 16 + (lane & 15);
                int dcol = p * 16 + ((lane >> 4) << 3);
                uint32_t bh[4], bl[4];
                ldsm_x4_t(bh[0], bh[1], bh[2], bh[3], uVh + (krow * KSTR + dcol) * 2);
                ldsm_x4_t(bl[0], bl[1], bl[2], bl[3], uVl + (krow * KSTR + dcol) * 2);
                mma16816h(oacc[2 * p],     pa[s4], bh + 0);
                mma16816h(oacc[2 * p],     pa[s4], bl + 0);
                mma16816h(oacc[2 * p + 1], pa[s4], bh + 2);
                mma16816h(oacc[2 * p + 1], pa[s4], bl + 2);
            }
        }
        __syncthreads();
    }

    // ---- epilogue: normalize, split fp16 hi/lo into Wo-GEMM A buffers ----
    float inv0 = 1.0f / l0, inv1 = 1.0f / l1;
    int t0 = qt * BQA + row0 + g;
#pragma unroll
    for (int nt = 0; nt < 16; nt++) {
        int d = nt * 8 + 2 * tg;
        float o0 = oacc[nt][0] * inv0, o1 = oacc[nt][1] * inv0;
        float o2 = oacc[nt][2] * inv1, o3 = oacc[nt][3] * inv1;
        size_t i0 = ((size_t)b * TT + t0) * KDIM + (size_t)h * DD + d;
        size_t i1 = ((size_t)b * TT + t0 + 8) * KDIM + (size_t)h * DD + d;
        float h0 = __half2float(__float2half_rn(o0));
        float h1 = __half2float(__float2half_rn(o1));
        float h2 = __half2float(__float2half_rn(o2));
        float h3 = __half2float(__float2half_rn(o3));
        *(uint32_t*)(Ohi + i0) = pack_h2(o0, o1);
        *(uint32_t*)(Olo + i0) = pack_h2(o0 - h0, o1 - h1);
        *(uint32_t*)(Ohi + i1) = pack_h2(o2, o3);
        *(uint32_t*)(Olo + i1) = pack_h2(o2 - h2, o3 - h3);
    }
}

// ---------------- launch ------------------------------------------------------
extern "C" void kernel_launch(void* const* d_in, const int* in_sizes, int n_in,
                              void* d_out, int out_size) {
    const float* hidden = (const float*)d_in[0];
    const float* Wqkv   = (const float*)d_in[1];
    const float* Wo     = (const float*)d_in[2];
    const float* qw     = (const float*)d_in[3];
    const float* kw     = (const float*)d_in[4];
    float* out = (float*)d_out;

    float *qkv, *rq, *rk, *G;
    __half *ahi, *alo, *b16, *vh, *vl;
    cudaGetSymbolAddress((void**)&qkv, g_qkv);
    cudaGetSymbolAddress((void**)&ahi, g_ahi);
    cudaGetSymbolAddress((void**)&alo, g_alo);
    cudaGetSymbolAddress((void**)&b16, g_b16);
    cudaGetSymbolAddress((void**)&vh,  g_vh);
    cudaGetSymbolAddress((void**)&vl,  g_vl);
    cudaGetSymbolAddress((void**)&rq,  g_rq);
    cudaGetSymbolAddress((void**)&rk,  g_rk);
    cudaGetSymbolAddress((void**)&G,   g_G);

    cudaFuncSetAttribute(attn_hmma, cudaFuncAttributeMaxDynamicSharedMemorySize,
                         ATT_SMEM);
    cudaFuncSetAttribute(hmma_gemm, cudaFuncAttributeMaxDynamicSharedMemorySize,
                         GEMM_SMEM);

    // 0) analytic rope-kernel table
    {
        dim3 grid(32, HH);
        build_G<<<grid, 128>>>(qw, kw, G);
    }

    // 1) convert inputs: hidden -> fp16 hi/lo (A), Wqkv -> fp16 (B)
    cvt_hilo16<<<1024, 256>>>(hidden, ahi, alo, (size_t)MT * KDIM);
    cvt_16<<<1024, 256>>>(Wqkv, b16, (size_t)QKV_OUT * KDIM);

    // 2) QKV projection (fp16 2-pass)
    {
        dim3 grid(QKV_OUT / 128, MT / 128);
        hmma_gemm<<<grid, 256, GEMM_SMEM>>>(ahi, alo, b16, qkv, QKV_OUT);
    }

    // 3) norm scalars + V fp16 hi/lo
    {
        dim3 grid(MT, HH + 2 * KVH);
        rnorm_kernel<<<grid, DD>>>(qkv, rq, rk, vh, vl);
    }

    // 4) Attention (analytic S + fp16 HMMA PV) -> hi/lo into Wo-GEMM A buffers
    {
        dim3 grid(TT / BQA, HH, BB);
        attn_hmma<<<grid, 256, ATT_SMEM>>>(rq, rk, G, vh, vl, ahi, alo);
    }

    // 5) Output projection (fp16 2-pass)
    cvt_16<<<1024, 256>>>(Wo, b16, (size_t)HID * KDIM);
    {
        dim3 grid(HID / 128, MT / 128);
        hmma_gemm<<<grid, 256, GEMM_SMEM>>>(ahi, alo, b16, out, HID);
    }
}